// round 13
// baseline (speedup 1.0000x reference)
#include <cuda_runtime.h>
#include <cuda_bf16.h>
#include <math.h>
#include <stdint.h>

// ---------------- problem constants ----------------
#define HEADS   24
#define HDIM    128
#define DIM     3072
#define S_TXT   512
#define S_IMG   2048
#define S_TOT   2560
#define EPS     1e-5f
#define QK_SCALE 0.08838834764831845f
#define C2EXP   (QK_SCALE * 1.44269504088896f)

#define LK2         6144            // 2*DIM : [hi|lo] packed K
#define APITCH      72
#define STAGE_ELEMS (2 * 128 * APITCH)
#define STAGE_BYTES (STAGE_ELEMS * 2)       // 36864
#define SMEM_BYTES  (2 * STAGE_BYTES)       // 73728 -> 2 CTAs/SM

// flash tiling
#define QP          264
#define FQ          64
#define FKV         32
#define FL_STAGE_E  (2 * FKV * QP)
#define FL_STAGE_B  (FL_STAGE_E * 2)
#define FL_SMEM     ((FQ + 4 * FKV) * QP * 2)  // 101376 B
#define NKV         (S_TOT / FKV)

// ---------------- scratch ----------------
__device__ __nv_bfloat16  g_acat[(size_t)S_TOT * LK2];
__device__ __nv_bfloat16  g_qg[(size_t)HEADS * S_TOT * 256];
__device__ __nv_bfloat16  g_kg[(size_t)HEADS * S_TOT * 256];
__device__ __nv_bfloat16  g_vg[(size_t)HEADS * S_TOT * 256];
__device__ __nv_bfloat16  g_ocat[(size_t)S_TOT * LK2];
__device__ __nv_bfloat16  g_wcat[8][(size_t)DIM * LK2];

// ---------------- helpers ----------------
struct bf16x4 { __nv_bfloat162 a, b; };

__device__ __forceinline__ void split4(float4 v, bf16x4& hi, bf16x4& lo) {
    __nv_bfloat162 h01 = __floats2bfloat162_rn(v.x, v.y);
    __nv_bfloat162 h23 = __floats2bfloat162_rn(v.z, v.w);
    float2 f01 = __bfloat1622float2(h01);
    float2 f23 = __bfloat1622float2(h23);
    hi.a = h01; hi.b = h23;
    lo.a = __floats2bfloat162_rn(v.x - f01.x, v.y - f01.y);
    lo.b = __floats2bfloat162_rn(v.z - f23.x, v.w - f23.y);
}
__device__ __forceinline__ uint32_t smem_u32(const void* p) {
    return static_cast<uint32_t>(__cvta_generic_to_shared(p));
}
__device__ __forceinline__ void cp16(void* dst, const void* src) {
    asm volatile("cp.async.cg.shared.global [%0], [%1], 16;"
                 :: "r"(smem_u32(dst)), "l"(src));
}
__device__ __forceinline__ void cp_commit() { asm volatile("cp.async.commit_group;"); }
template<int N>
__device__ __forceinline__ void cp_wait() {
    asm volatile("cp.async.wait_group %0;" :: "n"(N));
}
__device__ __forceinline__ void ldm_x4(uint32_t a, uint32_t& r0, uint32_t& r1,
                                       uint32_t& r2, uint32_t& r3) {
    asm volatile("ldmatrix.sync.aligned.m8n8.x4.shared.b16 {%0,%1,%2,%3}, [%4];"
                 : "=r"(r0), "=r"(r1), "=r"(r2), "=r"(r3) : "r"(a));
}
__device__ __forceinline__ void ldm_x4t(uint32_t a, uint32_t& r0, uint32_t& r1,
                                        uint32_t& r2, uint32_t& r3) {
    asm volatile("ldmatrix.sync.aligned.m8n8.x4.trans.shared.b16 {%0,%1,%2,%3}, [%4];"
                 : "=r"(r0), "=r"(r1), "=r"(r2), "=r"(r3) : "r"(a));
}
__device__ __forceinline__ void mma16816(float* c,
                                         uint32_t a0, uint32_t a1, uint32_t a2, uint32_t a3,
                                         uint32_t b0, uint32_t b1) {
    asm volatile("mma.sync.aligned.m16n8k16.row.col.f32.bf16.bf16.f32 "
                 "{%0,%1,%2,%3}, {%4,%5,%6,%7}, {%8,%9}, {%0,%1,%2,%3};"
                 : "+f"(c[0]), "+f"(c[1]), "+f"(c[2]), "+f"(c[3])
                 : "r"(a0), "r"(a1), "r"(a2), "r"(a3), "r"(b0), "r"(b1));
}
__device__ __forceinline__ uint32_t pack_bf16(float x, float y) {
    __nv_bfloat162 t = __floats2bfloat162_rn(x, y);
    return *reinterpret_cast<uint32_t*>(&t);
}

// ------- split-GEMM mainloop: 128 threads, 4 warps of 64x64 tiles -------
// acc[mi][nj][c]: mi 0..3 (16-row frags), nj 0..7 (8-col frags)
__device__ __forceinline__ void gemm_acc(
    const __nv_bfloat16* __restrict__ A, const __nv_bfloat16* __restrict__ B,
    float acc[4][8][4])
{
    extern __shared__ __nv_bfloat16 sm[];

    const int row0 = blockIdx.y * 128;
    const int tid  = threadIdx.x;
    const int lane = tid & 31;
    const int warp = tid >> 5;
    const int wm   = warp & 1;        // 64-row block
    const int wn   = warp >> 1;       // 64-col block

    auto load_stage = [&](int c, int stage) {
        __nv_bfloat16* As = sm + stage * STAGE_ELEMS;
        __nv_bfloat16* Bs = As + 128 * APITCH;
        const size_t ghi = (size_t)c * 32;
        const size_t glo = (size_t)DIM + c * 32;
        const __nv_bfloat16* ArowG = A + (size_t)(row0 + tid) * LK2;
        __nv_bfloat16* Ad = As + tid * APITCH;
#pragma unroll
        for (int i = 0; i < 4; i++) cp16(Ad + i * 8,      ArowG + ghi + i * 8);
#pragma unroll
        for (int i = 0; i < 4; i++) cp16(Ad + 32 + i * 8, ArowG + glo + i * 8);
        const __nv_bfloat16* BrowG = B + (size_t)tid * LK2;
        __nv_bfloat16* Bd = Bs + tid * APITCH;
#pragma unroll
        for (int i = 0; i < 4; i++) cp16(Bd + i * 8,      BrowG + ghi + i * 8);
#pragma unroll
        for (int i = 0; i < 4; i++) cp16(Bd + 32 + i * 8, BrowG + glo + i * 8);
        cp_commit();
    };

    const int m_off  = (lane & 7) + ((lane >> 3) & 1) * 8;
    const int k_off  = (lane >> 4) * 8;
    const int n_off  = (lane & 7) + (lane >> 4) * 8;
    const int kb_off = ((lane >> 3) & 1) * 8;

    uint32_t aBase[4], bBase[4];
#pragma unroll
    for (int mi = 0; mi < 4; mi++)
        aBase[mi] = smem_u32(sm + (wm * 64 + mi * 16 + m_off) * APITCH + k_off);
#pragma unroll
    for (int np = 0; np < 4; np++)
        bBase[np] = smem_u32(sm + 128 * APITCH + (wn * 64 + np * 16 + n_off) * APITCH + kb_off);

#pragma unroll
    for (int i = 0; i < 4; i++)
#pragma unroll
        for (int j = 0; j < 8; j++)
#pragma unroll
            for (int c = 0; c < 4; c++) acc[i][j][c] = 0.f;

    const int nc = DIM / 32;
    load_stage(0, 0);

    for (int c = 0; c < nc; c++) {
        if (c + 1 < nc) load_stage(c + 1, (c + 1) & 1);
        else            cp_commit();
        cp_wait<1>();
        __syncthreads();

        const uint32_t so = (uint32_t)(c & 1) * STAGE_BYTES;
#pragma unroll
        for (int ks = 0; ks < 2; ks++) {
            uint32_t Ah[4][4], Al[4][4];
#pragma unroll
            for (int mi = 0; mi < 4; mi++) {
                ldm_x4(aBase[mi] + so + ks * 32,      Ah[mi][0], Ah[mi][1], Ah[mi][2], Ah[mi][3]);
                ldm_x4(aBase[mi] + so + 64 + ks * 32, Al[mi][0], Al[mi][1], Al[mi][2], Al[mi][3]);
            }
#pragma unroll
            for (int np = 0; np < 4; np++) {
                uint32_t Bh[4], Bl[4];
                ldm_x4(bBase[np] + so + ks * 32,      Bh[0], Bh[1], Bh[2], Bh[3]);
                ldm_x4(bBase[np] + so + 64 + ks * 32, Bl[0], Bl[1], Bl[2], Bl[3]);
#pragma unroll
                for (int f = 0; f < 2; f++) {
                    const int nj = 2 * np + f;
#pragma unroll
                    for (int mi = 0; mi < 4; mi++) {
                        mma16816(acc[mi][nj], Ah[mi][0], Ah[mi][1], Ah[mi][2], Ah[mi][3],
                                 Bh[2 * f], Bh[2 * f + 1]);
                        mma16816(acc[mi][nj], Ah[mi][0], Ah[mi][1], Ah[mi][2], Ah[mi][3],
                                 Bl[2 * f], Bl[2 * f + 1]);
                        mma16816(acc[mi][nj], Al[mi][0], Al[mi][1], Al[mi][2], Al[mi][3],
                                 Bh[2 * f], Bh[2 * f + 1]);
                    }
                }
            }
        }
        __syncthreads();
    }
}

// ---------------- fused QKV: GEMM + bias + (RMSNorm + RoPE | V-split) -> qg/kg/vg ----------------
struct PArgs {
    const __nv_bfloat16 *Wimg, *Wenc;
    const float* biasEnc;
    const float* nwImg;                 // null for V
    const float* nwEnc;
    __nv_bfloat16* dst;                 // [h][s][256]
};

__global__ void __launch_bounds__(128, 2)
qkv_fused_k(const __nv_bfloat16* __restrict__ Aall, PArgs p0, PArgs p1, PArgs p2,
            const float* __restrict__ rcos, const float* __restrict__ rsin)
{
    PArgs p = (blockIdx.z == 0) ? p0 : (blockIdx.z == 1) ? p1 : p2;
    const int h    = blockIdx.x;
    const int row0 = blockIdx.y * 128;
    const bool enc = row0 < S_TXT;

    const __nv_bfloat16* B = (enc ? p.Wenc : p.Wimg) + (size_t)(h * 128) * LK2;

    float acc[4][8][4];
    gemm_acc(Aall, B, acc);

    const int tid  = threadIdx.x;
    const int lane = tid & 31;
    const int warp = tid >> 5;
    const int wm   = warp & 1;
    const int wn   = warp >> 1;
    const int rsel = lane >> 2;
    const int cp2  = (lane & 3) * 2;

    // ---- bias (enc rows only)
    if (enc && p.biasEnc) {
#pragma unroll
        for (int nj = 0; nj < 8; nj++) {
            const int col = h * 128 + wn * 64 + nj * 8 + cp2;
            const float b0 = p.biasEnc[col];
            const float b1 = p.biasEnc[col + 1];
#pragma unroll
            for (int mi = 0; mi < 4; mi++) {
                acc[mi][nj][0] += b0; acc[mi][nj][1] += b1;
                acc[mi][nj][2] += b0; acc[mi][nj][3] += b1;
            }
        }
    }

    const bool isV = (p.nwImg == nullptr);

    if (!isV) {
        extern __shared__ __nv_bfloat16 sm[];
        float* ss = reinterpret_cast<float*>(sm);     // [128] row sumsq
        if (tid < 128) ss[tid] = 0.f;
        __syncthreads();

        float s[4][2];
#pragma unroll
        for (int mi = 0; mi < 4; mi++) { s[mi][0] = 0.f; s[mi][1] = 0.f; }
#pragma unroll
        for (int mi = 0; mi < 4; mi++)
#pragma unroll
            for (int nj = 0; nj < 8; nj++) {
                s[mi][0] += acc[mi][nj][0] * acc[mi][nj][0] + acc[mi][nj][1] * acc[mi][nj][1];
                s[mi][1] += acc[mi][nj][2] * acc[mi][nj][2] + acc[mi][nj][3] * acc[mi][nj][3];
            }
#pragma unroll
        for (int off = 1; off <= 2; off <<= 1)
#pragma unroll
            for (int mi = 0; mi < 4; mi++) {
                s[mi][0] += __shfl_xor_sync(0xffffffffu, s[mi][0], off);
                s[mi][1] += __shfl_xor_sync(0xffffffffu, s[mi][1], off);
            }
        if ((lane & 3) == 0) {
#pragma unroll
            for (int mi = 0; mi < 4; mi++) {
                atomicAdd(&ss[wm * 64 + mi * 16 + rsel],     s[mi][0]);
                atomicAdd(&ss[wm * 64 + mi * 16 + rsel + 8], s[mi][1]);
            }
        }
        __syncthreads();

        const float* nw = enc ? p.nwEnc : p.nwImg;
#pragma unroll
        for (int mi = 0; mi < 4; mi++)
#pragma unroll
            for (int half = 0; half < 2; half++) {
                const int lr = wm * 64 + mi * 16 + rsel + half * 8;
                const int srow = row0 + lr;
                const float inv = rsqrtf(ss[lr] * (1.f / HDIM) + EPS);
                __nv_bfloat16* base = p.dst + ((size_t)h * S_TOT + srow) * 256;
#pragma unroll
                for (int nj = 0; nj < 8; nj++) {
                    const int d = wn * 64 + nj * 8 + cp2;
                    const float v0 = acc[mi][nj][half * 2 + 0];
                    const float v1 = acc[mi][nj][half * 2 + 1];
                    const float y0 = v0 * inv * nw[d];
                    const float y1 = v1 * inv * nw[d + 1];
                    const float c0 = rcos[(size_t)srow * HDIM + d];
                    const float c1 = rcos[(size_t)srow * HDIM + d + 1];
                    const float t0 = rsin[(size_t)srow * HDIM + d];
                    const float t1 = rsin[(size_t)srow * HDIM + d + 1];
                    const float o0 = y0 * c0 - y1 * t0;
                    const float o1 = y1 * c1 + y0 * t1;
                    __nv_bfloat162 hi = __floats2bfloat162_rn(o0, o1);
                    float2 f = __bfloat1622float2(hi);
                    __nv_bfloat162 lo = __floats2bfloat162_rn(o0 - f.x, o1 - f.y);
                    *reinterpret_cast<__nv_bfloat162*>(base + d)       = hi;
                    *reinterpret_cast<__nv_bfloat162*>(base + 128 + d) = lo;
                }
            }
    } else {
#pragma unroll
        for (int mi = 0; mi < 4; mi++)
#pragma unroll
            for (int half = 0; half < 2; half++) {
                const int lr = wm * 64 + mi * 16 + rsel + half * 8;
                const int srow = row0 + lr;
                __nv_bfloat16* base = p.dst + ((size_t)h * S_TOT + srow) * 256;
#pragma unroll
                for (int nj = 0; nj < 8; nj++) {
                    const int d = wn * 64 + nj * 8 + cp2;
                    const float o0 = acc[mi][nj][half * 2 + 0];
                    const float o1 = acc[mi][nj][half * 2 + 1];
                    __nv_bfloat162 hi = __floats2bfloat162_rn(o0, o1);
                    float2 f = __bfloat1622float2(hi);
                    __nv_bfloat162 lo = __floats2bfloat162_rn(o0 - f.x, o1 - f.y);
                    *reinterpret_cast<__nv_bfloat162*>(base + d)       = hi;
                    *reinterpret_cast<__nv_bfloat162*>(base + 128 + d) = lo;
                }
            }
    }
}

// ---------------- fused output projections ----------------
__global__ void __launch_bounds__(128, 2)
outproj_k(const __nv_bfloat16* __restrict__ A,
          const __nv_bfloat16* __restrict__ Wo,  const float* __restrict__ bo,
          const __nv_bfloat16* __restrict__ Wao, const float* __restrict__ bao,
          float* __restrict__ out)
{
    const int r0 = blockIdx.y * 128;
    const bool encRows = r0 < S_TXT;
    const __nv_bfloat16* B = (encRows ? Wao : Wo) + (size_t)(blockIdx.x * 128) * LK2;
    const float* bias = encRows ? bao : bo;
    float* C = encRows ? out + (size_t)S_IMG * DIM : out - (size_t)S_TXT * DIM;

    float acc[4][8][4];
    gemm_acc(A, B, acc);

    const int tid  = threadIdx.x;
    const int lane = tid & 31;
    const int warp = tid >> 5;
    const int wm   = warp & 1;
    const int wn   = warp >> 1;
    const int col0 = blockIdx.x * 128;

#pragma unroll
    for (int mi = 0; mi < 4; mi++) {
#pragma unroll
        for (int nj = 0; nj < 8; nj++) {
            const int row = r0 + wm * 64 + mi * 16 + (lane >> 2);
            const int col = col0 + wn * 64 + nj * 8 + (lane & 3) * 2;
            const float b0 = bias[col];
            const float b1 = bias[col + 1];
            float2 v0 = { acc[mi][nj][0] + b0, acc[mi][nj][1] + b1 };
            float2 v1 = { acc[mi][nj][2] + b0, acc[mi][nj][3] + b1 };
            *reinterpret_cast<float2*>(&C[(size_t)row * DIM + col])       = v0;
            *reinterpret_cast<float2*>(&C[(size_t)(row + 8) * DIM + col]) = v1;
        }
    }
}

// ---------------- converts ----------------
__global__ void __launch_bounds__(256)
conv_hl_k(const float* __restrict__ in, __nv_bfloat16* __restrict__ out, int M, int rowOff)
{
    const int idx = blockIdx.x * 256 + threadIdx.x;
    const int tot = M * (DIM / 4);
    if (idx >= tot) return;
    const int m = idx / (DIM / 4);
    const int c = (idx % (DIM / 4)) * 4;
    float4 v = *reinterpret_cast<const float4*>(in + (size_t)m * DIM + c);
    bf16x4 hi, lo;
    split4(v, hi, lo);
    __nv_bfloat16* base = out + (size_t)(rowOff + m) * LK2 + c;
    *reinterpret_cast<bf16x4*>(base)       = hi;
    *reinterpret_cast<bf16x4*>(base + DIM) = lo;
}

struct W8 { const float* p[8]; };
__global__ void __launch_bounds__(256)
conv_w8_k(W8 w, __nv_bfloat16* __restrict__ out)
{
    const float* in = w.p[blockIdx.z];
    __nv_bfloat16* o = out + (size_t)blockIdx.z * DIM * LK2;
    const int idx = blockIdx.x * 256 + threadIdx.x;
    if (idx >= DIM * (DIM / 4)) return;
    const int m = idx / (DIM / 4);
    const int c = (idx % (DIM / 4)) * 4;
    float4 v = *reinterpret_cast<const float4*>(in + (size_t)m * DIM + c);
    bf16x4 hi, lo;
    split4(v, hi, lo);
    __nv_bfloat16* base = o + (size_t)m * LK2 + c;
    *reinterpret_cast<bf16x4*>(base)       = hi;
    *reinterpret_cast<bf16x4*>(base + DIM) = lo;
}

// ---------------- flash attention (unchanged) ----------------
__global__ void __launch_bounds__(128, 2)
flash_k(const __nv_bfloat16* __restrict__ qg, const __nv_bfloat16* __restrict__ kg,
        const __nv_bfloat16* __restrict__ vg, __nv_bfloat16* __restrict__ ocat)
{
    extern __shared__ __nv_bfloat16 sm[];
    const int h  = blockIdx.y;
    const int q0 = blockIdx.x * FQ;
    const int tid  = threadIdx.x;
    const int lane = tid & 31;
    const int warp = tid >> 5;

    const __nv_bfloat16* qh_base = qg + ((size_t)h * S_TOT + q0) * 256;
    const __nv_bfloat16* kh_base = kg + (size_t)h * S_TOT * 256;
    const __nv_bfloat16* vh_base = vg + (size_t)h * S_TOT * 256;

    __nv_bfloat16* Qs  = sm;
    __nv_bfloat16* KV0 = sm + FQ * QP;

#pragma unroll
    for (int i = 0; i < 16; i++) {
        int idx = tid + i * 128;
        int r = idx >> 5, cc = (idx & 31) * 8;
        cp16(Qs + r * QP + cc, qh_base + (size_t)r * 256 + cc);
    }

    auto loadKV = [&](int it, int st) {
        __nv_bfloat16* Ks = KV0 + st * FL_STAGE_E;
        __nv_bfloat16* Vs = Ks + FKV * QP;
        const __nv_bfloat16* kb = kh_base + (size_t)(it * FKV) * 256;
        const __nv_bfloat16* vb = vh_base + (size_t)(it * FKV) * 256;
#pragma unroll
        for (int i = 0; i < 8; i++) {
            int idx = tid + i * 128;
            int r = idx >> 5, cc = (idx & 31) * 8;
            cp16(Ks + r * QP + cc, kb + (size_t)r * 256 + cc);
        }
#pragma unroll
        for (int i = 0; i < 8; i++) {
            int idx = tid + i * 128;
            int r = idx >> 5, cc = (idx & 31) * 8;
            cp16(Vs + r * QP + cc, vb + (size_t)r * 256 + cc);
        }
        cp_commit();
    };

    loadKV(0, 0);
    loadKV(1, 1);

    const int m_off  = (lane & 7) + ((lane >> 3) & 1) * 8;
    const int k_off  = (lane >> 4) * 8;
    const int n_off  = (lane & 7) + (lane >> 4) * 8;
    const int kb_off = ((lane >> 3) & 1) * 8;
    const int t_krow = (lane & 7) + ((lane >> 3) & 1) * 8;
    const int t_noff = (lane >> 4) * 8;

    const uint32_t aQ = smem_u32(Qs + (warp * 16 + m_off) * QP + k_off);
    uint32_t kB[2], vB[8];
#pragma unroll
    for (int np = 0; np < 2; np++)
        kB[np] = smem_u32(KV0 + (np * 16 + n_off) * QP + kb_off);
#pragma unroll
    for (int np = 0; np < 8; np++)
        vB[np] = smem_u32(KV0 + FKV * QP + t_krow * QP + np * 16 + t_noff);

    uint32_t qhf[8][4], qlf[8][4];
    float oAcc[16][4];
#pragma unroll
    for (int j = 0; j < 16; j++)
#pragma unroll
        for (int c = 0; c < 4; c++) oAcc[j][c] = 0.f;
    float mrow[2] = { -1e30f, -1e30f };
    float lrow[2] = { 0.f, 0.f };

    for (int it = 0; it < NKV; it++) {
        cp_wait<1>();
        __syncthreads();

        if (it == 0) {
#pragma unroll
            for (int ks = 0; ks < 8; ks++) {
                ldm_x4(aQ + ks * 32,       qhf[ks][0], qhf[ks][1], qhf[ks][2], qhf[ks][3]);
                ldm_x4(aQ + 256 + ks * 32, qlf[ks][0], qlf[ks][1], qlf[ks][2], qlf[ks][3]);
            }
        }

        const uint32_t so = (uint32_t)(it & 1) * FL_STAGE_B;

        float sAcc[4][4];
#pragma unroll
        for (int j = 0; j < 4; j++)
#pragma unroll
            for (int c = 0; c < 4; c++) sAcc[j][c] = 0.f;

#pragma unroll
        for (int ks = 0; ks < 8; ks++) {
#pragma unroll
            for (int np = 0; np < 2; np++) {
                uint32_t kh[4], kl[4];
                ldm_x4(kB[np] + so + ks * 32,       kh[0], kh[1], kh[2], kh[3]);
                ldm_x4(kB[np] + so + 256 + ks * 32, kl[0], kl[1], kl[2], kl[3]);
#pragma unroll
                for (int f = 0; f < 2; f++) {
                    float* acc = sAcc[2 * np + f];
                    mma16816(acc, qhf[ks][0], qhf[ks][1], qhf[ks][2], qhf[ks][3], kh[2 * f], kh[2 * f + 1]);
                    mma16816(acc, qhf[ks][0], qhf[ks][1], qhf[ks][2], qhf[ks][3], kl[2 * f], kl[2 * f + 1]);
                    mma16816(acc, qlf[ks][0], qlf[ks][1], qlf[ks][2], qlf[ks][3], kh[2 * f], kh[2 * f + 1]);
                }
            }
        }

        float rmax0 = -1e30f, rmax1 = -1e30f;
#pragma unroll
        for (int f = 0; f < 4; f++) {
            rmax0 = fmaxf(rmax0, fmaxf(sAcc[f][0], sAcc[f][1]));
            rmax1 = fmaxf(rmax1, fmaxf(sAcc[f][2], sAcc[f][3]));
        }
#pragma unroll
        for (int off = 1; off <= 2; off <<= 1) {
            rmax0 = fmaxf(rmax0, __shfl_xor_sync(0xffffffffu, rmax0, off));
            rmax1 = fmaxf(rmax1, __shfl_xor_sync(0xffffffffu, rmax1, off));
        }
        float mnew0 = fmaxf(mrow[0], rmax0);
        float mnew1 = fmaxf(mrow[1], rmax1);
        float cf0 = exp2f((mrow[0] - mnew0) * C2EXP);
        float cf1 = exp2f((mrow[1] - mnew1) * C2EXP);
        mrow[0] = mnew0; mrow[1] = mnew1;

#pragma unroll
        for (int j = 0; j < 16; j++) {
            oAcc[j][0] *= cf0; oAcc[j][1] *= cf0;
            oAcc[j][2] *= cf1; oAcc[j][3] *= cf1;
        }

        float sum0 = 0.f, sum1 = 0.f;
        uint32_t ph[2][4], pl[2][4];
#pragma unroll
        for (int ks = 0; ks < 2; ks++) {
            float p[8];
#pragma unroll
            for (int f = 0; f < 2; f++) {
                float* s = sAcc[2 * ks + f];
                p[4 * f + 0] = exp2f((s[0] - mnew0) * C2EXP);
                p[4 * f + 1] = exp2f((s[1] - mnew0) * C2EXP);
                p[4 * f + 2] = exp2f((s[2] - mnew1) * C2EXP);
                p[4 * f + 3] = exp2f((s[3] - mnew1) * C2EXP);
            }
            sum0 += p[0] + p[1] + p[4] + p[5];
            sum1 += p[2] + p[3] + p[6] + p[7];
            ph[ks][0] = pack_bf16(p[0], p[1]);
            ph[ks][1] = pack_bf16(p[2], p[3]);
            ph[ks][2] = pack_bf16(p[4], p[5]);
            ph[ks][3] = pack_bf16(p[6], p[7]);
            float r0 = p[0] - __bfloat162float(__float2bfloat16_rn(p[0]));
            float r1 = p[1] - __bfloat162float(__float2bfloat16_rn(p[1]));
            float r2 = p[2] - __bfloat162float(__float2bfloat16_rn(p[2]));
            float r3 = p[3] - __bfloat162float(__float2bfloat16_rn(p[3]));
            float r4 = p[4] - __bfloat162float(__float2bfloat16_rn(p[4]));
            float r5 = p[5] - __bfloat162float(__float2bfloat16_rn(p[5]));
            float r6 = p[6] - __bfloat162float(__float2bfloat16_rn(p[6]));
            float r7 = p[7] - __bfloat162float(__float2bfloat16_rn(p[7]));
            pl[ks][0] = pack_bf16(r0, r1);
            pl[ks][1] = pack_bf16(r2, r3);
            pl[ks][2] = pack_bf16(r4, r5);
            pl[ks][3] = pack_bf16(r6, r7);
        }
#pragma unroll
        for (int off = 1; off <= 2; off <<= 1) {
            sum0 += __shfl_xor_sync(0xffffffffu, sum0, off);
            sum1 += __shfl_xor_sync(0xffffffffu, sum1, off);
        }
        lrow[0] = lrow[0] * cf0 + sum0;
        lrow[1] = lrow[1] * cf1 + sum1;

#pragma unroll
        for (int ks = 0; ks < 2; ks++) {
            const uint32_t vo = so + ks * (16 * QP * 2);
#pragma unroll
            for (int np = 0; np < 8; np++) {
                uint32_t vh[4], vl[4];
                ldm_x4t(vB[np] + vo,       vh[0], vh[1], vh[2], vh[3]);
                ldm_x4t(vB[np] + vo + 256, vl[0], vl[1], vl[2], vl[3]);
#pragma unroll
                for (int f = 0; f < 2; f++) {
                    float* acc = oAcc[2 * np + f];
                    mma16816(acc, ph[ks][0], ph[ks][1], ph[ks][2], ph[ks][3], vh[2 * f], vh[2 * f + 1]);
                    mma16816(acc, pl[ks][0], pl[ks][1], pl[ks][2], pl[ks][3], vh[2 * f], vh[2 * f + 1]);
                    mma16816(acc, ph[ks][0], ph[ks][1], ph[ks][2], ph[ks][3], vl[2 * f], vl[2 * f + 1]);
                }
            }
        }

        __syncthreads();
        if (it + 2 < NKV) loadKV(it + 2, it & 1);
        else              cp_commit();
    }

    const float inv0 = 1.f / lrow[0];
    const float inv1 = 1.f / lrow[1];
    const int r0 = q0 + warp * 16 + (lane >> 2);
    const int colb = (lane & 3) * 2;
#pragma unroll
    for (int nj = 0; nj < 16; nj++) {
        const int col = h * HDIM + nj * 8 + colb;
        float o0 = oAcc[nj][0] * inv0, o1 = oAcc[nj][1] * inv0;
        float o2 = oAcc[nj][2] * inv1, o3 = oAcc[nj][3] * inv1;
        __nv_bfloat162 h01 = __floats2bfloat162_rn(o0, o1);
        __nv_bfloat162 h23 = __floats2bfloat162_rn(o2, o3);
        float2 f01 = __bfloat1622float2(h01);
        float2 f23 = __bfloat1622float2(h23);
        __nv_bfloat162 l01 = __floats2bfloat162_rn(o0 - f01.x, o1 - f01.y);
        __nv_bfloat162 l23 = __floats2bfloat162_rn(o2 - f23.x, o3 - f23.y);
        __nv_bfloat16* b0 = ocat + (size_t)r0 * LK2 + col;
        __nv_bfloat16* b1 = ocat + (size_t)(r0 + 8) * LK2 + col;
        *reinterpret_cast<__nv_bfloat162*>(b0)        = h01;
        *reinterpret_cast<__nv_bfloat162*>(b0 + DIM)  = l01;
        *reinterpret_cast<__nv_bfloat162*>(b1)        = h23;
        *reinterpret_cast<__nv_bfloat162*>(b1 + DIM)  = l23;
    }
}

// ---------------- launch ----------------
extern "C" void kernel_launch(void* const* d_in, const int* in_sizes, int n_in,
                              void* d_out, int out_size)
{
    (void)in_sizes; (void)n_in; (void)out_size;
    const float* x    = (const float*)d_in[0];
    const float* ehs  = (const float*)d_in[1];
    const float* rcos = (const float*)d_in[2];
    const float* rsin = (const float*)d_in[3];
    W8 w8 = {{ (const float*)d_in[4],  (const float*)d_in[5],
               (const float*)d_in[6],  (const float*)d_in[7],
               (const float*)d_in[8],  (const float*)d_in[9],
               (const float*)d_in[17], (const float*)d_in[19] }};
    const float* baq  = (const float*)d_in[10];
    const float* bak  = (const float*)d_in[11];
    const float* bav  = (const float*)d_in[12];
    const float* nqw  = (const float*)d_in[13];
    const float* nkw  = (const float*)d_in[14];
    const float* naqw = (const float*)d_in[15];
    const float* nakw = (const float*)d_in[16];
    const float* bo   = (const float*)d_in[18];
    const float* bao  = (const float*)d_in[20];
    float* out = (float*)d_out;

    __nv_bfloat16 *acat, *qg, *kg, *vg, *ocat, *wcat;
    cudaGetSymbolAddress((void**)&acat, g_acat);
    cudaGetSymbolAddress((void**)&qg,   g_qg);
    cudaGetSymbolAddress((void**)&kg,   g_kg);
    cudaGetSymbolAddress((void**)&vg,   g_vg);
    cudaGetSymbolAddress((void**)&ocat, g_ocat);
    cudaGetSymbolAddress((void**)&wcat, g_wcat);

    cudaFuncSetAttribute(qkv_fused_k, cudaFuncAttributeMaxDynamicSharedMemorySize, SMEM_BYTES);
    cudaFuncSetAttribute(outproj_k,   cudaFuncAttributeMaxDynamicSharedMemorySize, SMEM_BYTES);
    cudaFuncSetAttribute(flash_k,     cudaFuncAttributeMaxDynamicSharedMemorySize, FL_SMEM);

    const dim3 blk(256);
    const size_t WSTRIDE = (size_t)DIM * LK2;

    // converts (hi|lo layout)
    conv_hl_k<<<dim3((S_TXT * DIM / 4 + 255) / 256), blk>>>(ehs, acat, S_TXT, 0);
    conv_hl_k<<<dim3((S_IMG * DIM / 4 + 255) / 256), blk>>>(x,   acat, S_IMG, S_TXT);
    conv_w8_k<<<dim3((DIM * DIM / 4 + 255) / 256, 1, 8), blk>>>(w8, wcat);

    // fused QKV + bias + RMSNorm + RoPE + split -> qg/kg/vg
    {
        PArgs pq = { wcat + 0 * WSTRIDE, wcat + 3 * WSTRIDE, baq, nqw, naqw, qg };
        PArgs pk = { wcat + 1 * WSTRIDE, wcat + 4 * WSTRIDE, bak, nkw, nakw, kg };
        PArgs pv = { wcat + 2 * WSTRIDE, wcat + 5 * WSTRIDE, bav, nullptr, nullptr, vg };
        qkv_fused_k<<<dim3(HEADS, S_TOT / 128, 3), dim3(128), SMEM_BYTES>>>(
            acat, pq, pk, pv, rcos, rsin);
    }

    // fused attention -> ocat (hi|lo)
    flash_k<<<dim3(S_TOT / FQ, HEADS), dim3(128), FL_SMEM>>>(qg, kg, vg, ocat);

    // fused output projections
    outproj_k<<<dim3(DIM / 128, S_TOT / 128), dim3(128), SMEM_BYTES>>>(
        ocat, wcat + 6 * WSTRIDE, bo, wcat + 7 * WSTRIDE, bao, out);
}

// round 14
// speedup vs baseline: 1.0305x; 1.0305x over previous
#include <cuda_runtime.h>
#include <cuda_bf16.h>
#include <math.h>
#include <stdint.h>

// ---------------- problem constants ----------------
#define HEADS   24
#define HDIM    128
#define DIM     3072
#define S_TXT   512
#define S_IMG   2048
#define S_TOT   2560
#define EPS     1e-5f
#define QK_SCALE 0.08838834764831845f
#define C2EXP   (QK_SCALE * 1.44269504088896f)

#define LK2         6144            // 2*DIM : [hi|lo] packed K
#define APITCH      72
#define STAGE_ELEMS (2 * 128 * APITCH)
#define STAGE_BYTES (STAGE_ELEMS * 2)       // 36864
#define SMEM_BYTES  (3 * STAGE_BYTES)       // 110592; 2 CTAs/SM = 221KB <= 228KB

// flash tiling
#define QP          264
#define FQ          64
#define FKV         32
#define FL_STAGE_E  (2 * FKV * QP)
#define FL_STAGE_B  (FL_STAGE_E * 2)
#define FL_SMEM     ((FQ + 4 * FKV) * QP * 2)  // 101376 B
#define NKV         (S_TOT / FKV)

// ---------------- scratch ----------------
__device__ __nv_bfloat16  g_acat[(size_t)S_TOT * LK2];
__device__ __nv_bfloat16  g_qg[(size_t)HEADS * S_TOT * 256];
__device__ __nv_bfloat16  g_kg[(size_t)HEADS * S_TOT * 256];
__device__ __nv_bfloat16  g_vg[(size_t)HEADS * S_TOT * 256];
__device__ __nv_bfloat16  g_ocat[(size_t)S_TOT * LK2];
__device__ __nv_bfloat16  g_wcat[8][(size_t)DIM * LK2];

// ---------------- helpers ----------------
struct bf16x4 { __nv_bfloat162 a, b; };

__device__ __forceinline__ void split4(float4 v, bf16x4& hi, bf16x4& lo) {
    __nv_bfloat162 h01 = __floats2bfloat162_rn(v.x, v.y);
    __nv_bfloat162 h23 = __floats2bfloat162_rn(v.z, v.w);
    float2 f01 = __bfloat1622float2(h01);
    float2 f23 = __bfloat1622float2(h23);
    hi.a = h01; hi.b = h23;
    lo.a = __floats2bfloat162_rn(v.x - f01.x, v.y - f01.y);
    lo.b = __floats2bfloat162_rn(v.z - f23.x, v.w - f23.y);
}
__device__ __forceinline__ uint32_t smem_u32(const void* p) {
    return static_cast<uint32_t>(__cvta_generic_to_shared(p));
}
__device__ __forceinline__ void cp16(void* dst, const void* src) {
    asm volatile("cp.async.cg.shared.global [%0], [%1], 16;"
                 :: "r"(smem_u32(dst)), "l"(src));
}
__device__ __forceinline__ void cp_commit() { asm volatile("cp.async.commit_group;"); }
template<int N>
__device__ __forceinline__ void cp_wait() {
    asm volatile("cp.async.wait_group %0;" :: "n"(N));
}
__device__ __forceinline__ void ldm_x4(uint32_t a, uint32_t& r0, uint32_t& r1,
                                       uint32_t& r2, uint32_t& r3) {
    asm volatile("ldmatrix.sync.aligned.m8n8.x4.shared.b16 {%0,%1,%2,%3}, [%4];"
                 : "=r"(r0), "=r"(r1), "=r"(r2), "=r"(r3) : "r"(a));
}
__device__ __forceinline__ void ldm_x4t(uint32_t a, uint32_t& r0, uint32_t& r1,
                                        uint32_t& r2, uint32_t& r3) {
    asm volatile("ldmatrix.sync.aligned.m8n8.x4.trans.shared.b16 {%0,%1,%2,%3}, [%4];"
                 : "=r"(r0), "=r"(r1), "=r"(r2), "=r"(r3) : "r"(a));
}
__device__ __forceinline__ void mma16816(float* c,
                                         uint32_t a0, uint32_t a1, uint32_t a2, uint32_t a3,
                                         uint32_t b0, uint32_t b1) {
    asm volatile("mma.sync.aligned.m16n8k16.row.col.f32.bf16.bf16.f32 "
                 "{%0,%1,%2,%3}, {%4,%5,%6,%7}, {%8,%9}, {%0,%1,%2,%3};"
                 : "+f"(c[0]), "+f"(c[1]), "+f"(c[2]), "+f"(c[3])
                 : "r"(a0), "r"(a1), "r"(a2), "r"(a3), "r"(b0), "r"(b1));
}
__device__ __forceinline__ uint32_t pack_bf16(float x, float y) {
    __nv_bfloat162 t = __floats2bfloat162_rn(x, y);
    return *reinterpret_cast<uint32_t*>(&t);
}

// ------- split-GEMM mainloop: 256 threads, 8 warps of 32x64 tiles, 3-stage, 1 sync/chunk -------
__device__ __forceinline__ void gemm_acc(
    const __nv_bfloat16* __restrict__ A, const __nv_bfloat16* __restrict__ B,
    float acc[2][8][4])
{
    extern __shared__ __nv_bfloat16 sm[];

    const int row0 = blockIdx.y * 128;
    const int tid  = threadIdx.x;
    const int lane = tid & 31;
    const int warp = tid >> 5;
    const int wm   = warp & 3;
    const int wn   = warp >> 2;

    const int a_row = tid >> 1;
    const int a_sel = tid & 1;

    auto load_stage = [&](int c, int stage) {
        __nv_bfloat16* As = sm + stage * STAGE_ELEMS;
        __nv_bfloat16* Bs = As + 128 * APITCH;
        const size_t gcol = (size_t)a_sel * DIM + c * 32;
        const __nv_bfloat16* Ag = A + (size_t)(row0 + a_row) * LK2 + gcol;
        __nv_bfloat16* Ad = As + a_row * APITCH + a_sel * 32;
#pragma unroll
        for (int i = 0; i < 4; i++) cp16(Ad + i * 8, Ag + i * 8);
        const __nv_bfloat16* Bg = B + (size_t)a_row * LK2 + gcol;
        __nv_bfloat16* Bd = Bs + a_row * APITCH + a_sel * 32;
#pragma unroll
        for (int i = 0; i < 4; i++) cp16(Bd + i * 8, Bg + i * 8);
        cp_commit();
    };

    const int m_off  = (lane & 7) + ((lane >> 3) & 1) * 8;
    const int k_off  = (lane >> 4) * 8;
    const int n_off  = (lane & 7) + (lane >> 4) * 8;
    const int kb_off = ((lane >> 3) & 1) * 8;

    uint32_t aBase[2], bBase[4];
#pragma unroll
    for (int mi = 0; mi < 2; mi++)
        aBase[mi] = smem_u32(sm + (wm * 32 + mi * 16 + m_off) * APITCH + k_off);
#pragma unroll
    for (int np = 0; np < 4; np++)
        bBase[np] = smem_u32(sm + 128 * APITCH + (wn * 64 + np * 16 + n_off) * APITCH + kb_off);

#pragma unroll
    for (int i = 0; i < 2; i++)
#pragma unroll
        for (int j = 0; j < 8; j++)
#pragma unroll
            for (int c = 0; c < 4; c++) acc[i][j][c] = 0.f;

    const int nc = DIM / 32;
    load_stage(0, 0);
    load_stage(1, 1);

    int stage = 0;
    for (int c = 0; c < nc; c++) {
        cp_wait<1>();            // stage c complete (<=1 pending: c+1)
        __syncthreads();         // all warps finished compute(c-1); stage (c+2)%3 free
        if (c + 2 < nc) load_stage(c + 2, (c + 2) % 3);
        else            cp_commit();

        const uint32_t so = (uint32_t)stage * STAGE_BYTES;
#pragma unroll
        for (int ks = 0; ks < 2; ks++) {
            uint32_t Ah[2][4], Al[2][4];
#pragma unroll
            for (int mi = 0; mi < 2; mi++) {
                ldm_x4(aBase[mi] + so + ks * 32,      Ah[mi][0], Ah[mi][1], Ah[mi][2], Ah[mi][3]);
                ldm_x4(aBase[mi] + so + 64 + ks * 32, Al[mi][0], Al[mi][1], Al[mi][2], Al[mi][3]);
            }
#pragma unroll
            for (int np = 0; np < 4; np++) {
                uint32_t Bh[4], Bl[4];
                ldm_x4(bBase[np] + so + ks * 32,      Bh[0], Bh[1], Bh[2], Bh[3]);
                ldm_x4(bBase[np] + so + 64 + ks * 32, Bl[0], Bl[1], Bl[2], Bl[3]);
#pragma unroll
                for (int f = 0; f < 2; f++) {
                    const int nj = 2 * np + f;
#pragma unroll
                    for (int mi = 0; mi < 2; mi++) {
                        mma16816(acc[mi][nj], Ah[mi][0], Ah[mi][1], Ah[mi][2], Ah[mi][3],
                                 Bh[2 * f], Bh[2 * f + 1]);
                        mma16816(acc[mi][nj], Ah[mi][0], Ah[mi][1], Ah[mi][2], Ah[mi][3],
                                 Bl[2 * f], Bl[2 * f + 1]);
                        mma16816(acc[mi][nj], Al[mi][0], Al[mi][1], Al[mi][2], Al[mi][3],
                                 Bh[2 * f], Bh[2 * f + 1]);
                    }
                }
            }
        }
        stage = (stage + 1 == 3) ? 0 : stage + 1;
    }
}

// ---------------- fused QKV: GEMM + bias + (RMSNorm + RoPE | V-split) -> qg/kg/vg ----------------
struct PArgs {
    const __nv_bfloat16 *Wimg, *Wenc;
    const float* biasEnc;
    const float* nwImg;                 // null for V
    const float* nwEnc;
    __nv_bfloat16* dst;                 // [h][s][256]
};

__global__ void __launch_bounds__(256, 2)
qkv_fused_k(const __nv_bfloat16* __restrict__ Aall, PArgs p0, PArgs p1, PArgs p2,
            const float* __restrict__ rcos, const float* __restrict__ rsin)
{
    PArgs p = (blockIdx.z == 0) ? p0 : (blockIdx.z == 1) ? p1 : p2;
    const int h    = blockIdx.x;
    const int row0 = blockIdx.y * 128;
    const bool enc = row0 < S_TXT;

    const __nv_bfloat16* B = (enc ? p.Wenc : p.Wimg) + (size_t)(h * 128) * LK2;

    float acc[2][8][4];
    gemm_acc(Aall, B, acc);

    const int tid  = threadIdx.x;
    const int lane = tid & 31;
    const int warp = tid >> 5;
    const int wm   = warp & 3;
    const int wn   = warp >> 2;
    const int rsel = lane >> 2;
    const int cp2  = (lane & 3) * 2;

    if (enc && p.biasEnc) {
#pragma unroll
        for (int nj = 0; nj < 8; nj++) {
            const int col = h * 128 + wn * 64 + nj * 8 + cp2;
            const float b0 = p.biasEnc[col];
            const float b1 = p.biasEnc[col + 1];
#pragma unroll
            for (int mi = 0; mi < 2; mi++) {
                acc[mi][nj][0] += b0; acc[mi][nj][1] += b1;
                acc[mi][nj][2] += b0; acc[mi][nj][3] += b1;
            }
        }
    }

    const bool isV = (p.nwImg == nullptr);

    if (!isV) {
        extern __shared__ __nv_bfloat16 sm[];
        float* ss = reinterpret_cast<float*>(sm);     // [128] row sumsq
        __syncthreads();                               // mainloop reads finished
        if (tid < 128) ss[tid] = 0.f;
        __syncthreads();

        float s[2][2] = {{0.f, 0.f}, {0.f, 0.f}};
#pragma unroll
        for (int mi = 0; mi < 2; mi++)
#pragma unroll
            for (int nj = 0; nj < 8; nj++) {
                s[mi][0] += acc[mi][nj][0] * acc[mi][nj][0] + acc[mi][nj][1] * acc[mi][nj][1];
                s[mi][1] += acc[mi][nj][2] * acc[mi][nj][2] + acc[mi][nj][3] * acc[mi][nj][3];
            }
#pragma unroll
        for (int off = 1; off <= 2; off <<= 1) {
            s[0][0] += __shfl_xor_sync(0xffffffffu, s[0][0], off);
            s[0][1] += __shfl_xor_sync(0xffffffffu, s[0][1], off);
            s[1][0] += __shfl_xor_sync(0xffffffffu, s[1][0], off);
            s[1][1] += __shfl_xor_sync(0xffffffffu, s[1][1], off);
        }
        if ((lane & 3) == 0) {
            atomicAdd(&ss[wm * 32 + rsel],          s[0][0]);
            atomicAdd(&ss[wm * 32 + rsel + 8],      s[0][1]);
            atomicAdd(&ss[wm * 32 + 16 + rsel],     s[1][0]);
            atomicAdd(&ss[wm * 32 + 16 + rsel + 8], s[1][1]);
        }
        __syncthreads();

        const float* nw = enc ? p.nwEnc : p.nwImg;
#pragma unroll
        for (int mi = 0; mi < 2; mi++)
#pragma unroll
            for (int half = 0; half < 2; half++) {
                const int lr = wm * 32 + mi * 16 + rsel + half * 8;
                const int srow = row0 + lr;
                const float inv = rsqrtf(ss[lr] * (1.f / HDIM) + EPS);
                __nv_bfloat16* base = p.dst + ((size_t)h * S_TOT + srow) * 256;
#pragma unroll
                for (int nj = 0; nj < 8; nj++) {
                    const int d = wn * 64 + nj * 8 + cp2;
                    const float v0 = acc[mi][nj][half * 2 + 0];
                    const float v1 = acc[mi][nj][half * 2 + 1];
                    const float y0 = v0 * inv * nw[d];
                    const float y1 = v1 * inv * nw[d + 1];
                    const float c0 = rcos[(size_t)srow * HDIM + d];
                    const float c1 = rcos[(size_t)srow * HDIM + d + 1];
                    const float t0 = rsin[(size_t)srow * HDIM + d];
                    const float t1 = rsin[(size_t)srow * HDIM + d + 1];
                    const float o0 = y0 * c0 - y1 * t0;
                    const float o1 = y1 * c1 + y0 * t1;
                    __nv_bfloat162 hi = __floats2bfloat162_rn(o0, o1);
                    float2 f = __bfloat1622float2(hi);
                    __nv_bfloat162 lo = __floats2bfloat162_rn(o0 - f.x, o1 - f.y);
                    *reinterpret_cast<__nv_bfloat162*>(base + d)       = hi;
                    *reinterpret_cast<__nv_bfloat162*>(base + 128 + d) = lo;
                }
            }
    } else {
#pragma unroll
        for (int mi = 0; mi < 2; mi++)
#pragma unroll
            for (int half = 0; half < 2; half++) {
                const int lr = wm * 32 + mi * 16 + rsel + half * 8;
                const int srow = row0 + lr;
                __nv_bfloat16* base = p.dst + ((size_t)h * S_TOT + srow) * 256;
#pragma unroll
                for (int nj = 0; nj < 8; nj++) {
                    const int d = wn * 64 + nj * 8 + cp2;
                    const float o0 = acc[mi][nj][half * 2 + 0];
                    const float o1 = acc[mi][nj][half * 2 + 1];
                    __nv_bfloat162 hi = __floats2bfloat162_rn(o0, o1);
                    float2 f = __bfloat1622float2(hi);
                    __nv_bfloat162 lo = __floats2bfloat162_rn(o0 - f.x, o1 - f.y);
                    *reinterpret_cast<__nv_bfloat162*>(base + d)       = hi;
                    *reinterpret_cast<__nv_bfloat162*>(base + 128 + d) = lo;
                }
            }
    }
}

// ---------------- fused output projections ----------------
__global__ void __launch_bounds__(256, 2)
outproj_k(const __nv_bfloat16* __restrict__ A,
          const __nv_bfloat16* __restrict__ Wo,  const float* __restrict__ bo,
          const __nv_bfloat16* __restrict__ Wao, const float* __restrict__ bao,
          float* __restrict__ out)
{
    const int r0 = blockIdx.y * 128;
    const bool encRows = r0 < S_TXT;
    const __nv_bfloat16* B = (encRows ? Wao : Wo) + (size_t)(blockIdx.x * 128) * LK2;
    const float* bias = encRows ? bao : bo;
    float* C = encRows ? out + (size_t)S_IMG * DIM : out - (size_t)S_TXT * DIM;

    float acc[2][8][4];
    gemm_acc(A, B, acc);

    const int tid  = threadIdx.x;
    const int lane = tid & 31;
    const int warp = tid >> 5;
    const int wm   = warp & 3;
    const int wn   = warp >> 2;
    const int col0 = blockIdx.x * 128;

#pragma unroll
    for (int mi = 0; mi < 2; mi++) {
#pragma unroll
        for (int nj = 0; nj < 8; nj++) {
            const int row = r0 + wm * 32 + mi * 16 + (lane >> 2);
            const int col = col0 + wn * 64 + nj * 8 + (lane & 3) * 2;
            const float b0 = bias[col];
            const float b1 = bias[col + 1];
            float2 v0 = { acc[mi][nj][0] + b0, acc[mi][nj][1] + b1 };
            float2 v1 = { acc[mi][nj][2] + b0, acc[mi][nj][3] + b1 };
            *reinterpret_cast<float2*>(&C[(size_t)row * DIM + col])       = v0;
            *reinterpret_cast<float2*>(&C[(size_t)(row + 8) * DIM + col]) = v1;
        }
    }
}

// ---------------- converts ----------------
__global__ void __launch_bounds__(256)
conv_hl_k(const float* __restrict__ in, __nv_bfloat16* __restrict__ out, int M, int rowOff)
{
    const int idx = blockIdx.x * 256 + threadIdx.x;
    const int tot = M * (DIM / 4);
    if (idx >= tot) return;
    const int m = idx / (DIM / 4);
    const int c = (idx % (DIM / 4)) * 4;
    float4 v = *reinterpret_cast<const float4*>(in + (size_t)m * DIM + c);
    bf16x4 hi, lo;
    split4(v, hi, lo);
    __nv_bfloat16* base = out + (size_t)(rowOff + m) * LK2 + c;
    *reinterpret_cast<bf16x4*>(base)       = hi;
    *reinterpret_cast<bf16x4*>(base + DIM) = lo;
}

struct W8 { const float* p[8]; };
__global__ void __launch_bounds__(256)
conv_w8_k(W8 w, __nv_bfloat16* __restrict__ out)
{
    const float* in = w.p[blockIdx.z];
    __nv_bfloat16* o = out + (size_t)blockIdx.z * DIM * LK2;
    const int idx = blockIdx.x * 256 + threadIdx.x;
    if (idx >= DIM * (DIM / 4)) return;
    const int m = idx / (DIM / 4);
    const int c = (idx % (DIM / 4)) * 4;
    float4 v = *reinterpret_cast<const float4*>(in + (size_t)m * DIM + c);
    bf16x4 hi, lo;
    split4(v, hi, lo);
    __nv_bfloat16* base = o + (size_t)m * LK2 + c;
    *reinterpret_cast<bf16x4*>(base)       = hi;
    *reinterpret_cast<bf16x4*>(base + DIM) = lo;
}

// ---------------- flash attention (unchanged) ----------------
__global__ void __launch_bounds__(128, 2)
flash_k(const __nv_bfloat16* __restrict__ qg, const __nv_bfloat16* __restrict__ kg,
        const __nv_bfloat16* __restrict__ vg, __nv_bfloat16* __restrict__ ocat)
{
    extern __shared__ __nv_bfloat16 sm[];
    const int h  = blockIdx.y;
    const int q0 = blockIdx.x * FQ;
    const int tid  = threadIdx.x;
    const int lane = tid & 31;
    const int warp = tid >> 5;

    const __nv_bfloat16* qh_base = qg + ((size_t)h * S_TOT + q0) * 256;
    const __nv_bfloat16* kh_base = kg + (size_t)h * S_TOT * 256;
    const __nv_bfloat16* vh_base = vg + (size_t)h * S_TOT * 256;

    __nv_bfloat16* Qs  = sm;
    __nv_bfloat16* KV0 = sm + FQ * QP;

#pragma unroll
    for (int i = 0; i < 16; i++) {
        int idx = tid + i * 128;
        int r = idx >> 5, cc = (idx & 31) * 8;
        cp16(Qs + r * QP + cc, qh_base + (size_t)r * 256 + cc);
    }

    auto loadKV = [&](int it, int st) {
        __nv_bfloat16* Ks = KV0 + st * FL_STAGE_E;
        __nv_bfloat16* Vs = Ks + FKV * QP;
        const __nv_bfloat16* kb = kh_base + (size_t)(it * FKV) * 256;
        const __nv_bfloat16* vb = vh_base + (size_t)(it * FKV) * 256;
#pragma unroll
        for (int i = 0; i < 8; i++) {
            int idx = tid + i * 128;
            int r = idx >> 5, cc = (idx & 31) * 8;
            cp16(Ks + r * QP + cc, kb + (size_t)r * 256 + cc);
        }
#pragma unroll
        for (int i = 0; i < 8; i++) {
            int idx = tid + i * 128;
            int r = idx >> 5, cc = (idx & 31) * 8;
            cp16(Vs + r * QP + cc, vb + (size_t)r * 256 + cc);
        }
        cp_commit();
    };

    loadKV(0, 0);
    loadKV(1, 1);

    const int m_off  = (lane & 7) + ((lane >> 3) & 1) * 8;
    const int k_off  = (lane >> 4) * 8;
    const int n_off  = (lane & 7) + (lane >> 4) * 8;
    const int kb_off = ((lane >> 3) & 1) * 8;
    const int t_krow = (lane & 7) + ((lane >> 3) & 1) * 8;
    const int t_noff = (lane >> 4) * 8;

    const uint32_t aQ = smem_u32(Qs + (warp * 16 + m_off) * QP + k_off);
    uint32_t kB[2], vB[8];
#pragma unroll
    for (int np = 0; np < 2; np++)
        kB[np] = smem_u32(KV0 + (np * 16 + n_off) * QP + kb_off);
#pragma unroll
    for (int np = 0; np < 8; np++)
        vB[np] = smem_u32(KV0 + FKV * QP + t_krow * QP + np * 16 + t_noff);

    uint32_t qhf[8][4], qlf[8][4];
    float oAcc[16][4];
#pragma unroll
    for (int j = 0; j < 16; j++)
#pragma unroll
        for (int c = 0; c < 4; c++) oAcc[j][c] = 0.f;
    float mrow[2] = { -1e30f, -1e30f };
    float lrow[2] = { 0.f, 0.f };

    for (int it = 0; it < NKV; it++) {
        cp_wait<1>();
        __syncthreads();

        if (it == 0) {
#pragma unroll
            for (int ks = 0; ks < 8; ks++) {
                ldm_x4(aQ + ks * 32,       qhf[ks][0], qhf[ks][1], qhf[ks][2], qhf[ks][3]);
                ldm_x4(aQ + 256 + ks * 32, qlf[ks][0], qlf[ks][1], qlf[ks][2], qlf[ks][3]);
            }
        }

        const uint32_t so = (uint32_t)(it & 1) * FL_STAGE_B;

        float sAcc[4][4];
#pragma unroll
        for (int j = 0; j < 4; j++)
#pragma unroll
            for (int c = 0; c < 4; c++) sAcc[j][c] = 0.f;

#pragma unroll
        for (int ks = 0; ks < 8; ks++) {
#pragma unroll
            for (int np = 0; np < 2; np++) {
                uint32_t kh[4], kl[4];
                ldm_x4(kB[np] + so + ks * 32,       kh[0], kh[1], kh[2], kh[3]);
                ldm_x4(kB[np] + so + 256 + ks * 32, kl[0], kl[1], kl[2], kl[3]);
#pragma unroll
                for (int f = 0; f < 2; f++) {
                    float* acc = sAcc[2 * np + f];
                    mma16816(acc, qhf[ks][0], qhf[ks][1], qhf[ks][2], qhf[ks][3], kh[2 * f], kh[2 * f + 1]);
                    mma16816(acc, qhf[ks][0], qhf[ks][1], qhf[ks][2], qhf[ks][3], kl[2 * f], kl[2 * f + 1]);
                    mma16816(acc, qlf[ks][0], qlf[ks][1], qlf[ks][2], qlf[ks][3], kh[2 * f], kh[2 * f + 1]);
                }
            }
        }

        float rmax0 = -1e30f, rmax1 = -1e30f;
#pragma unroll
        for (int f = 0; f < 4; f++) {
            rmax0 = fmaxf(rmax0, fmaxf(sAcc[f][0], sAcc[f][1]));
            rmax1 = fmaxf(rmax1, fmaxf(sAcc[f][2], sAcc[f][3]));
        }
#pragma unroll
        for (int off = 1; off <= 2; off <<= 1) {
            rmax0 = fmaxf(rmax0, __shfl_xor_sync(0xffffffffu, rmax0, off));
            rmax1 = fmaxf(rmax1, __shfl_xor_sync(0xffffffffu, rmax1, off));
        }
        float mnew0 = fmaxf(mrow[0], rmax0);
        float mnew1 = fmaxf(mrow[1], rmax1);
        float cf0 = exp2f((mrow[0] - mnew0) * C2EXP);
        float cf1 = exp2f((mrow[1] - mnew1) * C2EXP);
        mrow[0] = mnew0; mrow[1] = mnew1;

#pragma unroll
        for (int j = 0; j < 16; j++) {
            oAcc[j][0] *= cf0; oAcc[j][1] *= cf0;
            oAcc[j][2] *= cf1; oAcc[j][3] *= cf1;
        }

        float sum0 = 0.f, sum1 = 0.f;
        uint32_t ph[2][4], pl[2][4];
#pragma unroll
        for (int ks = 0; ks < 2; ks++) {
            float p[8];
#pragma unroll
            for (int f = 0; f < 2; f++) {
                float* s = sAcc[2 * ks + f];
                p[4 * f + 0] = exp2f((s[0] - mnew0) * C2EXP);
                p[4 * f + 1] = exp2f((s[1] - mnew0) * C2EXP);
                p[4 * f + 2] = exp2f((s[2] - mnew1) * C2EXP);
                p[4 * f + 3] = exp2f((s[3] - mnew1) * C2EXP);
            }
            sum0 += p[0] + p[1] + p[4] + p[5];
            sum1 += p[2] + p[3] + p[6] + p[7];
            ph[ks][0] = pack_bf16(p[0], p[1]);
            ph[ks][1] = pack_bf16(p[2], p[3]);
            ph[ks][2] = pack_bf16(p[4], p[5]);
            ph[ks][3] = pack_bf16(p[6], p[7]);
            float r0 = p[0] - __bfloat162float(__float2bfloat16_rn(p[0]));
            float r1 = p[1] - __bfloat162float(__float2bfloat16_rn(p[1]));
            float r2 = p[2] - __bfloat162float(__float2bfloat16_rn(p[2]));
            float r3 = p[3] - __bfloat162float(__float2bfloat16_rn(p[3]));
            float r4 = p[4] - __bfloat162float(__float2bfloat16_rn(p[4]));
            float r5 = p[5] - __bfloat162float(__float2bfloat16_rn(p[5]));
            float r6 = p[6] - __bfloat162float(__float2bfloat16_rn(p[6]));
            float r7 = p[7] - __bfloat162float(__float2bfloat16_rn(p[7]));
            pl[ks][0] = pack_bf16(r0, r1);
            pl[ks][1] = pack_bf16(r2, r3);
            pl[ks][2] = pack_bf16(r4, r5);
            pl[ks][3] = pack_bf16(r6, r7);
        }
#pragma unroll
        for (int off = 1; off <= 2; off <<= 1) {
            sum0 += __shfl_xor_sync(0xffffffffu, sum0, off);
            sum1 += __shfl_xor_sync(0xffffffffu, sum1, off);
        }
        lrow[0] = lrow[0] * cf0 + sum0;
        lrow[1] = lrow[1] * cf1 + sum1;

#pragma unroll
        for (int ks = 0; ks < 2; ks++) {
            const uint32_t vo = so + ks * (16 * QP * 2);
#pragma unroll
            for (int np = 0; np < 8; np++) {
                uint32_t vh[4], vl[4];
                ldm_x4t(vB[np] + vo,       vh[0], vh[1], vh[2], vh[3]);
                ldm_x4t(vB[np] + vo + 256, vl[0], vl[1], vl[2], vl[3]);
#pragma unroll
                for (int f = 0; f < 2; f++) {
                    float* acc = oAcc[2 * np + f];
                    mma16816(acc, ph[ks][0], ph[ks][1], ph[ks][2], ph[ks][3], vh[2 * f], vh[2 * f + 1]);
                    mma16816(acc, pl[ks][0], pl[ks][1], pl[ks][2], pl[ks][3], vh[2 * f], vh[2 * f + 1]);
                    mma16816(acc, ph[ks][0], ph[ks][1], ph[ks][2], ph[ks][3], vl[2 * f], vl[2 * f + 1]);
                }
            }
        }

        __syncthreads();
        if (it + 2 < NKV) loadKV(it + 2, it & 1);
        else              cp_commit();
    }

    const float inv0 = 1.f / lrow[0];
    const float inv1 = 1.f / lrow[1];
    const int r0 = q0 + warp * 16 + (lane >> 2);
    const int colb = (lane & 3) * 2;
#pragma unroll
    for (int nj = 0; nj < 16; nj++) {
        const int col = h * HDIM + nj * 8 + colb;
        float o0 = oAcc[nj][0] * inv0, o1 = oAcc[nj][1] * inv0;
        float o2 = oAcc[nj][2] * inv1, o3 = oAcc[nj][3] * inv1;
        __nv_bfloat162 h01 = __floats2bfloat162_rn(o0, o1);
        __nv_bfloat162 h23 = __floats2bfloat162_rn(o2, o3);
        float2 f01 = __bfloat1622float2(h01);
        float2 f23 = __bfloat1622float2(h23);
        __nv_bfloat162 l01 = __floats2bfloat162_rn(o0 - f01.x, o1 - f01.y);
        __nv_bfloat162 l23 = __floats2bfloat162_rn(o2 - f23.x, o3 - f23.y);
        __nv_bfloat16* b0 = ocat + (size_t)r0 * LK2 + col;
        __nv_bfloat16* b1 = ocat + (size_t)(r0 + 8) * LK2 + col;
        *reinterpret_cast<__nv_bfloat162*>(b0)        = h01;
        *reinterpret_cast<__nv_bfloat162*>(b0 + DIM)  = l01;
        *reinterpret_cast<__nv_bfloat162*>(b1)        = h23;
        *reinterpret_cast<__nv_bfloat162*>(b1 + DIM)  = l23;
    }
}

// ---------------- launch ----------------
extern "C" void kernel_launch(void* const* d_in, const int* in_sizes, int n_in,
                              void* d_out, int out_size)
{
    (void)in_sizes; (void)n_in; (void)out_size;
    const float* x    = (const float*)d_in[0];
    const float* ehs  = (const float*)d_in[1];
    const float* rcos = (const float*)d_in[2];
    const float* rsin = (const float*)d_in[3];
    W8 w8 = {{ (const float*)d_in[4],  (const float*)d_in[5],
               (const float*)d_in[6],  (const float*)d_in[7],
               (const float*)d_in[8],  (const float*)d_in[9],
               (const float*)d_in[17], (const float*)d_in[19] }};
    const float* baq  = (const float*)d_in[10];
    const float* bak  = (const float*)d_in[11];
    const float* bav  = (const float*)d_in[12];
    const float* nqw  = (const float*)d_in[13];
    const float* nkw  = (const float*)d_in[14];
    const float* naqw = (const float*)d_in[15];
    const float* nakw = (const float*)d_in[16];
    const float* bo   = (const float*)d_in[18];
    const float* bao  = (const float*)d_in[20];
    float* out = (float*)d_out;

    __nv_bfloat16 *acat, *qg, *kg, *vg, *ocat, *wcat;
    cudaGetSymbolAddress((void**)&acat, g_acat);
    cudaGetSymbolAddress((void**)&qg,   g_qg);
    cudaGetSymbolAddress((void**)&kg,   g_kg);
    cudaGetSymbolAddress((void**)&vg,   g_vg);
    cudaGetSymbolAddress((void**)&ocat, g_ocat);
    cudaGetSymbolAddress((void**)&wcat, g_wcat);

    cudaFuncSetAttribute(qkv_fused_k, cudaFuncAttributeMaxDynamicSharedMemorySize, SMEM_BYTES);
    cudaFuncSetAttribute(outproj_k,   cudaFuncAttributeMaxDynamicSharedMemorySize, SMEM_BYTES);
    cudaFuncSetAttribute(flash_k,     cudaFuncAttributeMaxDynamicSharedMemorySize, FL_SMEM);

    const dim3 blk(256);
    const size_t WSTRIDE = (size_t)DIM * LK2;

    // converts (hi|lo layout)
    conv_hl_k<<<dim3((S_TXT * DIM / 4 + 255) / 256), blk>>>(ehs, acat, S_TXT, 0);
    conv_hl_k<<<dim3((S_IMG * DIM / 4 + 255) / 256), blk>>>(x,   acat, S_IMG, S_TXT);
    conv_w8_k<<<dim3((DIM * DIM / 4 + 255) / 256, 1, 8), blk>>>(w8, wcat);

    // fused QKV + bias + RMSNorm + RoPE + split -> qg/kg/vg
    {
        PArgs pq = { wcat + 0 * WSTRIDE, wcat + 3 * WSTRIDE, baq, nqw, naqw, qg };
        PArgs pk = { wcat + 1 * WSTRIDE, wcat + 4 * WSTRIDE, bak, nkw, nakw, kg };
        PArgs pv = { wcat + 2 * WSTRIDE, wcat + 5 * WSTRIDE, bav, nullptr, nullptr, vg };
        qkv_fused_k<<<dim3(HEADS, S_TOT / 128, 3), blk, SMEM_BYTES>>>(
            acat, pq, pk, pv, rcos, rsin);
    }

    // fused attention -> ocat (hi|lo)
    flash_k<<<dim3(S_TOT / FQ, HEADS), dim3(128), FL_SMEM>>>(qg, kg, vg, ocat);

    // fused output projections
    outproj_k<<<dim3(DIM / 128, S_TOT / 128), blk, SMEM_BYTES>>>(
        ocat, wcat + 6 * WSTRIDE, bo, wcat + 7 * WSTRIDE, bao, out);
}

// round 15
// speedup vs baseline: 1.0313x; 1.0008x over previous
#include <cuda_runtime.h>
#include <cuda_bf16.h>
#include <math.h>
#include <stdint.h>

// ---------------- problem constants ----------------
#define HEADS   24
#define HDIM    128
#define DIM     3072
#define S_TXT   512
#define S_IMG   2048
#define S_TOT   2560
#define EPS     1e-5f
#define QK_SCALE 0.08838834764831845f
#define C2EXP   (QK_SCALE * 1.44269504088896f)

#define LK2         6144
#define APITCH      72
#define STAGE_ELEMS (2 * 128 * APITCH)
#define STAGE_BYTES (STAGE_ELEMS * 2)       // 36864
#define SMEM_BYTES  (2 * STAGE_BYTES)       // 73728 -> 2 CTAs/SM

// flash tiling
#define QP          264
#define FQ          64
#define FKV         32
#define FL_STAGE_E  (2 * FKV * QP)
#define FL_STAGE_B  (FL_STAGE_E * 2)
#define FL_SMEM     ((FQ + 4 * FKV) * QP * 2)  // 101376 B
#define NKV         (S_TOT / FKV)

// ---------------- scratch ----------------
__device__ __nv_bfloat16  g_acat[(size_t)S_TOT * LK2];
__device__ __nv_bfloat16  g_qg[(size_t)HEADS * S_TOT * 256];
__device__ __nv_bfloat16  g_kg[(size_t)HEADS * S_TOT * 256];
__device__ __nv_bfloat16  g_vg[(size_t)HEADS * S_TOT * 256];
__device__ __nv_bfloat16  g_ocat[(size_t)S_TOT * LK2];
__device__ __nv_bfloat16  g_wcat[8][(size_t)DIM * LK2];

// ---------------- helpers ----------------
struct bf16x4 { __nv_bfloat162 a, b; };

__device__ __forceinline__ void split4(float4 v, bf16x4& hi, bf16x4& lo) {
    __nv_bfloat162 h01 = __floats2bfloat162_rn(v.x, v.y);
    __nv_bfloat162 h23 = __floats2bfloat162_rn(v.z, v.w);
    float2 f01 = __bfloat1622float2(h01);
    float2 f23 = __bfloat1622float2(h23);
    hi.a = h01; hi.b = h23;
    lo.a = __floats2bfloat162_rn(v.x - f01.x, v.y - f01.y);
    lo.b = __floats2bfloat162_rn(v.z - f23.x, v.w - f23.y);
}
__device__ __forceinline__ uint32_t smem_u32(const void* p) {
    return static_cast<uint32_t>(__cvta_generic_to_shared(p));
}
__device__ __forceinline__ void cp16(void* dst, const void* src) {
    asm volatile("cp.async.cg.shared.global [%0], [%1], 16;"
                 :: "r"(smem_u32(dst)), "l"(src));
}
__device__ __forceinline__ void cp_commit() { asm volatile("cp.async.commit_group;"); }
template<int N>
__device__ __forceinline__ void cp_wait() {
    asm volatile("cp.async.wait_group %0;" :: "n"(N));
}
__device__ __forceinline__ void ldm_x4(uint32_t a, uint32_t& r0, uint32_t& r1,
                                       uint32_t& r2, uint32_t& r3) {
    asm volatile("ldmatrix.sync.aligned.m8n8.x4.shared.b16 {%0,%1,%2,%3}, [%4];"
                 : "=r"(r0), "=r"(r1), "=r"(r2), "=r"(r3) : "r"(a));
}
__device__ __forceinline__ void ldm_x4t(uint32_t a, uint32_t& r0, uint32_t& r1,
                                        uint32_t& r2, uint32_t& r3) {
    asm volatile("ldmatrix.sync.aligned.m8n8.x4.trans.shared.b16 {%0,%1,%2,%3}, [%4];"
                 : "=r"(r0), "=r"(r1), "=r"(r2), "=r"(r3) : "r"(a));
}
__device__ __forceinline__ void mma16816(float* c,
                                         uint32_t a0, uint32_t a1, uint32_t a2, uint32_t a3,
                                         uint32_t b0, uint32_t b1) {
    asm volatile("mma.sync.aligned.m16n8k16.row.col.f32.bf16.bf16.f32 "
                 "{%0,%1,%2,%3}, {%4,%5,%6,%7}, {%8,%9}, {%0,%1,%2,%3};"
                 : "+f"(c[0]), "+f"(c[1]), "+f"(c[2]), "+f"(c[3])
                 : "r"(a0), "r"(a1), "r"(a2), "r"(a3), "r"(b0), "r"(b1));
}
__device__ __forceinline__ uint32_t pack_bf16(float x, float y) {
    __nv_bfloat162 t = __floats2bfloat162_rn(x, y);
    return *reinterpret_cast<uint32_t*>(&t);
}

// ------- split-GEMM mainloop: 256 thr / 8 warps, 2-stage, term-major MMA order -------
__device__ __forceinline__ void gemm_acc(
    const __nv_bfloat16* __restrict__ A, const __nv_bfloat16* __restrict__ B,
    float acc[2][8][4])
{
    extern __shared__ __nv_bfloat16 sm[];

    const int row0 = blockIdx.y * 128;
    const int tid  = threadIdx.x;
    const int lane = tid & 31;
    const int warp = tid >> 5;
    const int wm   = warp & 3;
    const int wn   = warp >> 2;

    const int a_row = tid >> 1;
    const int a_sel = tid & 1;

    auto load_stage = [&](int c, int stage) {
        __nv_bfloat16* As = sm + stage * STAGE_ELEMS;
        __nv_bfloat16* Bs = As + 128 * APITCH;
        const size_t gcol = (size_t)a_sel * DIM + c * 32;
        const __nv_bfloat16* Ag = A + (size_t)(row0 + a_row) * LK2 + gcol;
        __nv_bfloat16* Ad = As + a_row * APITCH + a_sel * 32;
#pragma unroll
        for (int i = 0; i < 4; i++) cp16(Ad + i * 8, Ag + i * 8);
        const __nv_bfloat16* Bg = B + (size_t)a_row * LK2 + gcol;
        __nv_bfloat16* Bd = Bs + a_row * APITCH + a_sel * 32;
#pragma unroll
        for (int i = 0; i < 4; i++) cp16(Bd + i * 8, Bg + i * 8);
        cp_commit();
    };

    const int m_off  = (lane & 7) + ((lane >> 3) & 1) * 8;
    const int k_off  = (lane >> 4) * 8;
    const int n_off  = (lane & 7) + (lane >> 4) * 8;
    const int kb_off = ((lane >> 3) & 1) * 8;

    uint32_t aBase[2], bBase[4];
#pragma unroll
    for (int mi = 0; mi < 2; mi++)
        aBase[mi] = smem_u32(sm + (wm * 32 + mi * 16 + m_off) * APITCH + k_off);
#pragma unroll
    for (int np = 0; np < 4; np++)
        bBase[np] = smem_u32(sm + 128 * APITCH + (wn * 64 + np * 16 + n_off) * APITCH + kb_off);

#pragma unroll
    for (int i = 0; i < 2; i++)
#pragma unroll
        for (int j = 0; j < 8; j++)
#pragma unroll
            for (int c = 0; c < 4; c++) acc[i][j][c] = 0.f;

    const int nc = DIM / 32;
    load_stage(0, 0);

    for (int c = 0; c < nc; c++) {
        if (c + 1 < nc) load_stage(c + 1, (c + 1) & 1);
        else            cp_commit();
        cp_wait<1>();
        __syncthreads();

        const uint32_t so = (uint32_t)(c & 1) * STAGE_BYTES;
#pragma unroll
        for (int ks = 0; ks < 2; ks++) {
            uint32_t Ah[2][4], Al[2][4];
#pragma unroll
            for (int mi = 0; mi < 2; mi++) {
                ldm_x4(aBase[mi] + so + ks * 32,      Ah[mi][0], Ah[mi][1], Ah[mi][2], Ah[mi][3]);
                ldm_x4(aBase[mi] + so + 64 + ks * 32, Al[mi][0], Al[mi][1], Al[mi][2], Al[mi][3]);
            }
#pragma unroll
            for (int np = 0; np < 4; np++) {
                uint32_t Bh[4], Bl[4];
                ldm_x4(bBase[np] + so + ks * 32,      Bh[0], Bh[1], Bh[2], Bh[3]);
                ldm_x4(bBase[np] + so + 64 + ks * 32, Bl[0], Bl[1], Bl[2], Bl[3]);
                // term-major: 4 independent accs between same-acc revisits
#pragma unroll
                for (int f = 0; f < 2; f++)
#pragma unroll
                    for (int mi = 0; mi < 2; mi++)
                        mma16816(acc[mi][2 * np + f], Ah[mi][0], Ah[mi][1], Ah[mi][2], Ah[mi][3],
                                 Bh[2 * f], Bh[2 * f + 1]);
#pragma unroll
                for (int f = 0; f < 2; f++)
#pragma unroll
                    for (int mi = 0; mi < 2; mi++)
                        mma16816(acc[mi][2 * np + f], Ah[mi][0], Ah[mi][1], Ah[mi][2], Ah[mi][3],
                                 Bl[2 * f], Bl[2 * f + 1]);
#pragma unroll
                for (int f = 0; f < 2; f++)
#pragma unroll
                    for (int mi = 0; mi < 2; mi++)
                        mma16816(acc[mi][2 * np + f], Al[mi][0], Al[mi][1], Al[mi][2], Al[mi][3],
                                 Bh[2 * f], Bh[2 * f + 1]);
            }
        }
        __syncthreads();
    }
}

// ---------------- fused QKV: GEMM + bias + (RMSNorm + RoPE | V-split) ----------------
struct PArgs {
    const __nv_bfloat16 *Wimg, *Wenc;
    const float* biasEnc;
    const float* nwImg;                 // null for V
    const float* nwEnc;
    __nv_bfloat16* dst;                 // [h][s][256]
};

__global__ void __launch_bounds__(256, 2)
qkv_fused_k(const __nv_bfloat16* __restrict__ Aall, PArgs p0, PArgs p1, PArgs p2,
            const float* __restrict__ rcos, const float* __restrict__ rsin)
{
    PArgs p = (blockIdx.z == 0) ? p0 : (blockIdx.z == 1) ? p1 : p2;
    const int h    = blockIdx.x;
    const int row0 = blockIdx.y * 128;
    const bool enc = row0 < S_TXT;

    const __nv_bfloat16* B = (enc ? p.Wenc : p.Wimg) + (size_t)(h * 128) * LK2;

    float acc[2][8][4];
    gemm_acc(Aall, B, acc);

    const int tid  = threadIdx.x;
    const int lane = tid & 31;
    const int warp = tid >> 5;
    const int wm   = warp & 3;
    const int wn   = warp >> 2;
    const int rsel = lane >> 2;
    const int cp2  = (lane & 3) * 2;

    if (enc && p.biasEnc) {
#pragma unroll
        for (int nj = 0; nj < 8; nj++) {
            const int col = h * 128 + wn * 64 + nj * 8 + cp2;
            const float b0 = p.biasEnc[col];
            const float b1 = p.biasEnc[col + 1];
#pragma unroll
            for (int mi = 0; mi < 2; mi++) {
                acc[mi][nj][0] += b0; acc[mi][nj][1] += b1;
                acc[mi][nj][2] += b0; acc[mi][nj][3] += b1;
            }
        }
    }

    const bool isV = (p.nwImg == nullptr);

    if (!isV) {
        extern __shared__ __nv_bfloat16 sm[];
        float* ss = reinterpret_cast<float*>(sm);
        __syncthreads();
        if (tid < 128) ss[tid] = 0.f;
        __syncthreads();

        float s[2][2] = {{0.f, 0.f}, {0.f, 0.f}};
#pragma unroll
        for (int mi = 0; mi < 2; mi++)
#pragma unroll
            for (int nj = 0; nj < 8; nj++) {
                s[mi][0] += acc[mi][nj][0] * acc[mi][nj][0] + acc[mi][nj][1] * acc[mi][nj][1];
                s[mi][1] += acc[mi][nj][2] * acc[mi][nj][2] + acc[mi][nj][3] * acc[mi][nj][3];
            }
#pragma unroll
        for (int off = 1; off <= 2; off <<= 1) {
            s[0][0] += __shfl_xor_sync(0xffffffffu, s[0][0], off);
            s[0][1] += __shfl_xor_sync(0xffffffffu, s[0][1], off);
            s[1][0] += __shfl_xor_sync(0xffffffffu, s[1][0], off);
            s[1][1] += __shfl_xor_sync(0xffffffffu, s[1][1], off);
        }
        if ((lane & 3) == 0) {
            atomicAdd(&ss[wm * 32 + rsel],          s[0][0]);
            atomicAdd(&ss[wm * 32 + rsel + 8],      s[0][1]);
            atomicAdd(&ss[wm * 32 + 16 + rsel],     s[1][0]);
            atomicAdd(&ss[wm * 32 + 16 + rsel + 8], s[1][1]);
        }
        __syncthreads();

        const float* nw = enc ? p.nwEnc : p.nwImg;
#pragma unroll
        for (int mi = 0; mi < 2; mi++)
#pragma unroll
            for (int half = 0; half < 2; half++) {
                const int lr = wm * 32 + mi * 16 + rsel + half * 8;
                const int srow = row0 + lr;
                const float inv = rsqrtf(ss[lr] * (1.f / HDIM) + EPS);
                __nv_bfloat16* base = p.dst + ((size_t)h * S_TOT + srow) * 256;
#pragma unroll
                for (int nj = 0; nj < 8; nj++) {
                    const int d = wn * 64 + nj * 8 + cp2;
                    const float v0 = acc[mi][nj][half * 2 + 0];
                    const float v1 = acc[mi][nj][half * 2 + 1];
                    const float y0 = v0 * inv * nw[d];
                    const float y1 = v1 * inv * nw[d + 1];
                    const float c0 = rcos[(size_t)srow * HDIM + d];
                    const float c1 = rcos[(size_t)srow * HDIM + d + 1];
                    const float t0 = rsin[(size_t)srow * HDIM + d];
                    const float t1 = rsin[(size_t)srow * HDIM + d + 1];
                    const float o0 = y0 * c0 - y1 * t0;
                    const float o1 = y1 * c1 + y0 * t1;
                    __nv_bfloat162 hi = __floats2bfloat162_rn(o0, o1);
                    float2 f = __bfloat1622float2(hi);
                    __nv_bfloat162 lo = __floats2bfloat162_rn(o0 - f.x, o1 - f.y);
                    *reinterpret_cast<__nv_bfloat162*>(base + d)       = hi;
                    *reinterpret_cast<__nv_bfloat162*>(base + 128 + d) = lo;
                }
            }
    } else {
#pragma unroll
        for (int mi = 0; mi < 2; mi++)
#pragma unroll
            for (int half = 0; half < 2; half++) {
                const int lr = wm * 32 + mi * 16 + rsel + half * 8;
                const int srow = row0 + lr;
                __nv_bfloat16* base = p.dst + ((size_t)h * S_TOT + srow) * 256;
#pragma unroll
                for (int nj = 0; nj < 8; nj++) {
                    const int d = wn * 64 + nj * 8 + cp2;
                    const float o0 = acc[mi][nj][half * 2 + 0];
                    const float o1 = acc[mi][nj][half * 2 + 1];
                    __nv_bfloat162 hi = __floats2bfloat162_rn(o0, o1);
                    float2 f = __bfloat1622float2(hi);
                    __nv_bfloat162 lo = __floats2bfloat162_rn(o0 - f.x, o1 - f.y);
                    *reinterpret_cast<__nv_bfloat162*>(base + d)       = hi;
                    *reinterpret_cast<__nv_bfloat162*>(base + 128 + d) = lo;
                }
            }
    }
}

// ---------------- fused output projections ----------------
__global__ void __launch_bounds__(256, 2)
outproj_k(const __nv_bfloat16* __restrict__ A,
          const __nv_bfloat16* __restrict__ Wo,  const float* __restrict__ bo,
          const __nv_bfloat16* __restrict__ Wao, const float* __restrict__ bao,
          float* __restrict__ out)
{
    const int r0 = blockIdx.y * 128;
    const bool encRows = r0 < S_TXT;
    const __nv_bfloat16* B = (encRows ? Wao : Wo) + (size_t)(blockIdx.x * 128) * LK2;
    const float* bias = encRows ? bao : bo;
    float* C = encRows ? out + (size_t)S_IMG * DIM : out - (size_t)S_TXT * DIM;

    float acc[2][8][4];
    gemm_acc(A, B, acc);

    const int tid  = threadIdx.x;
    const int lane = tid & 31;
    const int warp = tid >> 5;
    const int wm   = warp & 3;
    const int wn   = warp >> 2;
    const int col0 = blockIdx.x * 128;

#pragma unroll
    for (int mi = 0; mi < 2; mi++) {
#pragma unroll
        for (int nj = 0; nj < 8; nj++) {
            const int row = r0 + wm * 32 + mi * 16 + (lane >> 2);
            const int col = col0 + wn * 64 + nj * 8 + (lane & 3) * 2;
            const float b0 = bias[col];
            const float b1 = bias[col + 1];
            float2 v0 = { acc[mi][nj][0] + b0, acc[mi][nj][1] + b1 };
            float2 v1 = { acc[mi][nj][2] + b0, acc[mi][nj][3] + b1 };
            *reinterpret_cast<float2*>(&C[(size_t)row * DIM + col])       = v0;
            *reinterpret_cast<float2*>(&C[(size_t)(row + 8) * DIM + col]) = v1;
        }
    }
}

// ---------------- converts ----------------
__global__ void __launch_bounds__(256)
conv_hl_k(const float* __restrict__ in, __nv_bfloat16* __restrict__ out, int M, int rowOff)
{
    const int idx = blockIdx.x * 256 + threadIdx.x;
    const int tot = M * (DIM / 4);
    if (idx >= tot) return;
    const int m = idx / (DIM / 4);
    const int c = (idx % (DIM / 4)) * 4;
    float4 v = *reinterpret_cast<const float4*>(in + (size_t)m * DIM + c);
    bf16x4 hi, lo;
    split4(v, hi, lo);
    __nv_bfloat16* base = out + (size_t)(rowOff + m) * LK2 + c;
    *reinterpret_cast<bf16x4*>(base)       = hi;
    *reinterpret_cast<bf16x4*>(base + DIM) = lo;
}

struct W8 { const float* p[8]; };
__global__ void __launch_bounds__(256)
conv_w8_k(W8 w, __nv_bfloat16* __restrict__ out)
{
    const float* in = w.p[blockIdx.z];
    __nv_bfloat16* o = out + (size_t)blockIdx.z * DIM * LK2;
    const int idx = blockIdx.x * 256 + threadIdx.x;
    if (idx >= DIM * (DIM / 4)) return;
    const int m = idx / (DIM / 4);
    const int c = (idx % (DIM / 4)) * 4;
    float4 v = *reinterpret_cast<const float4*>(in + (size_t)m * DIM + c);
    bf16x4 hi, lo;
    split4(v, hi, lo);
    __nv_bfloat16* base = o + (size_t)m * LK2 + c;
    *reinterpret_cast<bf16x4*>(base)       = hi;
    *reinterpret_cast<bf16x4*>(base + DIM) = lo;
}

// ---------------- flash attention (term-major MMA order) ----------------
__global__ void __launch_bounds__(128, 2)
flash_k(const __nv_bfloat16* __restrict__ qg, const __nv_bfloat16* __restrict__ kg,
        const __nv_bfloat16* __restrict__ vg, __nv_bfloat16* __restrict__ ocat)
{
    extern __shared__ __nv_bfloat16 sm[];
    const int h  = blockIdx.y;
    const int q0 = blockIdx.x * FQ;
    const int tid  = threadIdx.x;
    const int lane = tid & 31;
    const int warp = tid >> 5;

    const __nv_bfloat16* qh_base = qg + ((size_t)h * S_TOT + q0) * 256;
    const __nv_bfloat16* kh_base = kg + (size_t)h * S_TOT * 256;
    const __nv_bfloat16* vh_base = vg + (size_t)h * S_TOT * 256;

    __nv_bfloat16* Qs  = sm;
    __nv_bfloat16* KV0 = sm + FQ * QP;

#pragma unroll
    for (int i = 0; i < 16; i++) {
        int idx = tid + i * 128;
        int r = idx >> 5, cc = (idx & 31) * 8;
        cp16(Qs + r * QP + cc, qh_base + (size_t)r * 256 + cc);
    }

    auto loadKV = [&](int it, int st) {
        __nv_bfloat16* Ks = KV0 + st * FL_STAGE_E;
        __nv_bfloat16* Vs = Ks + FKV * QP;
        const __nv_bfloat16* kb = kh_base + (size_t)(it * FKV) * 256;
        const __nv_bfloat16* vb = vh_base + (size_t)(it * FKV) * 256;
#pragma unroll
        for (int i = 0; i < 8; i++) {
            int idx = tid + i * 128;
            int r = idx >> 5, cc = (idx & 31) * 8;
            cp16(Ks + r * QP + cc, kb + (size_t)r * 256 + cc);
        }
#pragma unroll
        for (int i = 0; i < 8; i++) {
            int idx = tid + i * 128;
            int r = idx >> 5, cc = (idx & 31) * 8;
            cp16(Vs + r * QP + cc, vb + (size_t)r * 256 + cc);
        }
        cp_commit();
    };

    loadKV(0, 0);
    loadKV(1, 1);

    const int m_off  = (lane & 7) + ((lane >> 3) & 1) * 8;
    const int k_off  = (lane >> 4) * 8;
    const int n_off  = (lane & 7) + (lane >> 4) * 8;
    const int kb_off = ((lane >> 3) & 1) * 8;
    const int t_krow = (lane & 7) + ((lane >> 3) & 1) * 8;
    const int t_noff = (lane >> 4) * 8;

    const uint32_t aQ = smem_u32(Qs + (warp * 16 + m_off) * QP + k_off);
    uint32_t kB[2], vB[8];
#pragma unroll
    for (int np = 0; np < 2; np++)
        kB[np] = smem_u32(KV0 + (np * 16 + n_off) * QP + kb_off);
#pragma unroll
    for (int np = 0; np < 8; np++)
        vB[np] = smem_u32(KV0 + FKV * QP + t_krow * QP + np * 16 + t_noff);

    uint32_t qhf[8][4], qlf[8][4];
    float oAcc[16][4];
#pragma unroll
    for (int j = 0; j < 16; j++)
#pragma unroll
        for (int c = 0; c < 4; c++) oAcc[j][c] = 0.f;
    float mrow[2] = { -1e30f, -1e30f };
    float lrow[2] = { 0.f, 0.f };

    for (int it = 0; it < NKV; it++) {
        cp_wait<1>();
        __syncthreads();

        if (it == 0) {
#pragma unroll
            for (int ks = 0; ks < 8; ks++) {
                ldm_x4(aQ + ks * 32,       qhf[ks][0], qhf[ks][1], qhf[ks][2], qhf[ks][3]);
                ldm_x4(aQ + 256 + ks * 32, qlf[ks][0], qlf[ks][1], qlf[ks][2], qlf[ks][3]);
            }
        }

        const uint32_t so = (uint32_t)(it & 1) * FL_STAGE_B;

        float sAcc[4][4];
#pragma unroll
        for (int j = 0; j < 4; j++)
#pragma unroll
            for (int c = 0; c < 4; c++) sAcc[j][c] = 0.f;

        // ---- QK: hoist K frags for both np, issue term-major (gap 4)
#pragma unroll
        for (int ks = 0; ks < 8; ks++) {
            uint32_t kh[2][4], kl[2][4];
#pragma unroll
            for (int np = 0; np < 2; np++) {
                ldm_x4(kB[np] + so + ks * 32,       kh[np][0], kh[np][1], kh[np][2], kh[np][3]);
                ldm_x4(kB[np] + so + 256 + ks * 32, kl[np][0], kl[np][1], kl[np][2], kl[np][3]);
            }
#pragma unroll
            for (int np = 0; np < 2; np++)
#pragma unroll
                for (int f = 0; f < 2; f++)
                    mma16816(sAcc[2 * np + f], qhf[ks][0], qhf[ks][1], qhf[ks][2], qhf[ks][3],
                             kh[np][2 * f], kh[np][2 * f + 1]);
#pragma unroll
            for (int np = 0; np < 2; np++)
#pragma unroll
                for (int f = 0; f < 2; f++)
                    mma16816(sAcc[2 * np + f], qhf[ks][0], qhf[ks][1], qhf[ks][2], qhf[ks][3],
                             kl[np][2 * f], kl[np][2 * f + 1]);
#pragma unroll
            for (int np = 0; np < 2; np++)
#pragma unroll
                for (int f = 0; f < 2; f++)
                    mma16816(sAcc[2 * np + f], qlf[ks][0], qlf[ks][1], qlf[ks][2], qlf[ks][3],
                             kh[np][2 * f], kh[np][2 * f + 1]);
        }

        float rmax0 = -1e30f, rmax1 = -1e30f;
#pragma unroll
        for (int f = 0; f < 4; f++) {
            rmax0 = fmaxf(rmax0, fmaxf(sAcc[f][0], sAcc[f][1]));
            rmax1 = fmaxf(rmax1, fmaxf(sAcc[f][2], sAcc[f][3]));
        }
#pragma unroll
        for (int off = 1; off <= 2; off <<= 1) {
            rmax0 = fmaxf(rmax0, __shfl_xor_sync(0xffffffffu, rmax0, off));
            rmax1 = fmaxf(rmax1, __shfl_xor_sync(0xffffffffu, rmax1, off));
        }
        float mnew0 = fmaxf(mrow[0], rmax0);
        float mnew1 = fmaxf(mrow[1], rmax1);
        float cf0 = exp2f((mrow[0] - mnew0) * C2EXP);
        float cf1 = exp2f((mrow[1] - mnew1) * C2EXP);
        mrow[0] = mnew0; mrow[1] = mnew1;

#pragma unroll
        for (int j = 0; j < 16; j++) {
            oAcc[j][0] *= cf0; oAcc[j][1] *= cf0;
            oAcc[j][2] *= cf1; oAcc[j][3] *= cf1;
        }

        float sum0 = 0.f, sum1 = 0.f;
        uint32_t ph[2][4], pl[2][4];
#pragma unroll
        for (int ks = 0; ks < 2; ks++) {
            float p[8];
#pragma unroll
            for (int f = 0; f < 2; f++) {
                float* s = sAcc[2 * ks + f];
                p[4 * f + 0] = exp2f((s[0] - mnew0) * C2EXP);
                p[4 * f + 1] = exp2f((s[1] - mnew0) * C2EXP);
                p[4 * f + 2] = exp2f((s[2] - mnew1) * C2EXP);
                p[4 * f + 3] = exp2f((s[3] - mnew1) * C2EXP);
            }
            sum0 += p[0] + p[1] + p[4] + p[5];
            sum1 += p[2] + p[3] + p[6] + p[7];
            ph[ks][0] = pack_bf16(p[0], p[1]);
            ph[ks][1] = pack_bf16(p[2], p[3]);
            ph[ks][2] = pack_bf16(p[4], p[5]);
            ph[ks][3] = pack_bf16(p[6], p[7]);
            float r0 = p[0] - __bfloat162float(__float2bfloat16_rn(p[0]));
            float r1 = p[1] - __bfloat162float(__float2bfloat16_rn(p[1]));
            float r2 = p[2] - __bfloat162float(__float2bfloat16_rn(p[2]));
            float r3 = p[3] - __bfloat162float(__float2bfloat16_rn(p[3]));
            float r4 = p[4] - __bfloat162float(__float2bfloat16_rn(p[4]));
            float r5 = p[5] - __bfloat162float(__float2bfloat16_rn(p[5]));
            float r6 = p[6] - __bfloat162float(__float2bfloat16_rn(p[6]));
            float r7 = p[7] - __bfloat162float(__float2bfloat16_rn(p[7]));
            pl[ks][0] = pack_bf16(r0, r1);
            pl[ks][1] = pack_bf16(r2, r3);
            pl[ks][2] = pack_bf16(r4, r5);
            pl[ks][3] = pack_bf16(r6, r7);
        }
#pragma unroll
        for (int off = 1; off <= 2; off <<= 1) {
            sum0 += __shfl_xor_sync(0xffffffffu, sum0, off);
            sum1 += __shfl_xor_sync(0xffffffffu, sum1, off);
        }
        lrow[0] = lrow[0] * cf0 + sum0;
        lrow[1] = lrow[1] * cf1 + sum1;

        // ---- PV: term-major per (ks,np) pair (gap 2)
#pragma unroll
        for (int ks = 0; ks < 2; ks++) {
            const uint32_t vo = so + ks * (16 * QP * 2);
#pragma unroll
            for (int np = 0; np < 8; np++) {
                uint32_t vh[4], vl[4];
                ldm_x4t(vB[np] + vo,       vh[0], vh[1], vh[2], vh[3]);
                ldm_x4t(vB[np] + vo + 256, vl[0], vl[1], vl[2], vl[3]);
#pragma unroll
                for (int f = 0; f < 2; f++)
                    mma16816(oAcc[2 * np + f], ph[ks][0], ph[ks][1], ph[ks][2], ph[ks][3],
                             vh[2 * f], vh[2 * f + 1]);
#pragma unroll
                for (int f = 0; f < 2; f++)
                    mma16816(oAcc[2 * np + f], pl[ks][0], pl[ks][1], pl[ks][2], pl[ks][3],
                             vh[2 * f], vh[2 * f + 1]);
#pragma unroll
                for (int f = 0; f < 2; f++)
                    mma16816(oAcc[2 * np + f], ph[ks][0], ph[ks][1], ph[ks][2], ph[ks][3],
                             vl[2 * f], vl[2 * f + 1]);
            }
        }

        __syncthreads();
        if (it + 2 < NKV) loadKV(it + 2, it & 1);
        else              cp_commit();
    }

    const float inv0 = 1.f / lrow[0];
    const float inv1 = 1.f / lrow[1];
    const int r0 = q0 + warp * 16 + (lane >> 2);
    const int colb = (lane & 3) * 2;
#pragma unroll
    for (int nj = 0; nj < 16; nj++) {
        const int col = h * HDIM + nj * 8 + colb;
        float o0 = oAcc[nj][0] * inv0, o1 = oAcc[nj][1] * inv0;
        float o2 = oAcc[nj][2] * inv1, o3 = oAcc[nj][3] * inv1;
        __nv_bfloat162 h01 = __floats2bfloat162_rn(o0, o1);
        __nv_bfloat162 h23 = __floats2bfloat162_rn(o2, o3);
        float2 f01 = __bfloat1622float2(h01);
        float2 f23 = __bfloat1622float2(h23);
        __nv_bfloat162 l01 = __floats2bfloat162_rn(o0 - f01.x, o1 - f01.y);
        __nv_bfloat162 l23 = __floats2bfloat162_rn(o2 - f23.x, o3 - f23.y);
        __nv_bfloat16* b0 = ocat + (size_t)r0 * LK2 + col;
        __nv_bfloat16* b1 = ocat + (size_t)(r0 + 8) * LK2 + col;
        *reinterpret_cast<__nv_bfloat162*>(b0)        = h01;
        *reinterpret_cast<__nv_bfloat162*>(b0 + DIM)  = l01;
        *reinterpret_cast<__nv_bfloat162*>(b1)        = h23;
        *reinterpret_cast<__nv_bfloat162*>(b1 + DIM)  = l23;
    }
}

// ---------------- launch ----------------
extern "C" void kernel_launch(void* const* d_in, const int* in_sizes, int n_in,
                              void* d_out, int out_size)
{
    (void)in_sizes; (void)n_in; (void)out_size;
    const float* x    = (const float*)d_in[0];
    const float* ehs  = (const float*)d_in[1];
    const float* rcos = (const float*)d_in[2];
    const float* rsin = (const float*)d_in[3];
    W8 w8 = {{ (const float*)d_in[4],  (const float*)d_in[5],
               (const float*)d_in[6],  (const float*)d_in[7],
               (const float*)d_in[8],  (const float*)d_in[9],
               (const float*)d_in[17], (const float*)d_in[19] }};
    const float* baq  = (const float*)d_in[10];
    const float* bak  = (const float*)d_in[11];
    const float* bav  = (const float*)d_in[12];
    const float* nqw  = (const float*)d_in[13];
    const float* nkw  = (const float*)d_in[14];
    const float* naqw = (const float*)d_in[15];
    const float* nakw = (const float*)d_in[16];
    const float* bo   = (const float*)d_in[18];
    const float* bao  = (const float*)d_in[20];
    float* out = (float*)d_out;

    __nv_bfloat16 *acat, *qg, *kg, *vg, *ocat, *wcat;
    cudaGetSymbolAddress((void**)&acat, g_acat);
    cudaGetSymbolAddress((void**)&qg,   g_qg);
    cudaGetSymbolAddress((void**)&kg,   g_kg);
    cudaGetSymbolAddress((void**)&vg,   g_vg);
    cudaGetSymbolAddress((void**)&ocat, g_ocat);
    cudaGetSymbolAddress((void**)&wcat, g_wcat);

    cudaFuncSetAttribute(qkv_fused_k, cudaFuncAttributeMaxDynamicSharedMemorySize, SMEM_BYTES);
    cudaFuncSetAttribute(outproj_k,   cudaFuncAttributeMaxDynamicSharedMemorySize, SMEM_BYTES);
    cudaFuncSetAttribute(flash_k,     cudaFuncAttributeMaxDynamicSharedMemorySize, FL_SMEM);

    const dim3 blk(256);
    const size_t WSTRIDE = (size_t)DIM * LK2;

    conv_hl_k<<<dim3((S_TXT * DIM / 4 + 255) / 256), blk>>>(ehs, acat, S_TXT, 0);
    conv_hl_k<<<dim3((S_IMG * DIM / 4 + 255) / 256), blk>>>(x,   acat, S_IMG, S_TXT);
    conv_w8_k<<<dim3((DIM * DIM / 4 + 255) / 256, 1, 8), blk>>>(w8, wcat);

    {
        PArgs pq = { wcat + 0 * WSTRIDE, wcat + 3 * WSTRIDE, baq, nqw, naqw, qg };
        PArgs pk = { wcat + 1 * WSTRIDE, wcat + 4 * WSTRIDE, bak, nkw, nakw, kg };
        PArgs pv = { wcat + 2 * WSTRIDE, wcat + 5 * WSTRIDE, bav, nullptr, nullptr, vg };
        qkv_fused_k<<<dim3(HEADS, S_TOT / 128, 3), blk, SMEM_BYTES>>>(
            acat, pq, pk, pv, rcos, rsin);
    }

    flash_k<<<dim3(S_TOT / FQ, HEADS), dim3(128), FL_SMEM>>>(qg, kg, vg, ocat);

    outproj_k<<<dim3(DIM / 128, S_TOT / 128), blk, SMEM_BYTES>>>(
        ocat, wcat + 6 * WSTRIDE, bo, wcat + 7 * WSTRIDE, bao, out);
}

// round 16
// speedup vs baseline: 1.5418x; 1.4950x over previous
#include <cuda_runtime.h>
#include <cuda_fp16.h>
#include <math.h>
#include <stdint.h>

// ---------------- problem constants ----------------
#define HEADS   24
#define HDIM    128
#define DIM     3072
#define S_TXT   512
#define S_IMG   2048
#define S_TOT   2560
#define EPS     1e-5f
#define QK_SCALE 0.08838834764831845f
#define C2EXP   (QK_SCALE * 1.44269504088896f)

#define LK2         6144            // 2*DIM : [hi|lo] packed A-side K
#define APITCH      72              // A tile pitch (64 data + 8 pad)
#define BPITCH      40              // B tile pitch (32 data + 8 pad)
#define STAGE_ELEMS (128 * APITCH + 128 * BPITCH)   // 14336
#define STAGE_BYTES (STAGE_ELEMS * 2)               // 28672
#define SMEM_BYTES  (2 * STAGE_BYTES)               // 57344 -> 2 CTAs/SM

// flash tiling: Q 64 (hi|lo), KV 32 x 128 (hi only)
#define QP          264
#define KP          136
#define FQ          64
#define FKV         32
#define FL_STAGE_E  (2 * FKV * KP)                  // K+V elems = 8704
#define FL_STAGE_B  (FL_STAGE_E * 2)
#define FL_SMEM     ((FQ * QP + 2 * FL_STAGE_E) * 2)  // 68608 B
#define NKV         (S_TOT / FKV)

// ---------------- scratch ----------------
__device__ __half  g_acat[(size_t)S_TOT * LK2];
__device__ __half  g_qg[(size_t)HEADS * S_TOT * 256];   // hi|lo
__device__ __half  g_kg[(size_t)HEADS * S_TOT * 128];   // hi only
__device__ __half  g_vg[(size_t)HEADS * S_TOT * 128];   // hi only
__device__ __half  g_ocat[(size_t)S_TOT * LK2];
__device__ __half  g_wcat[8][(size_t)DIM * DIM];        // hi only

// ---------------- helpers ----------------
struct h4 { __half2 a, b; };

__device__ __forceinline__ void split4h(float4 v, h4& hi, h4& lo) {
    __half2 h01 = __floats2half2_rn(v.x, v.y);
    __half2 h23 = __floats2half2_rn(v.z, v.w);
    float2 f01 = __half22float2(h01);
    float2 f23 = __half22float2(h23);
    hi.a = h01; hi.b = h23;
    lo.a = __floats2half2_rn(v.x - f01.x, v.y - f01.y);
    lo.b = __floats2half2_rn(v.z - f23.x, v.w - f23.y);
}
__device__ __forceinline__ uint32_t smem_u32(const void* p) {
    return static_cast<uint32_t>(__cvta_generic_to_shared(p));
}
__device__ __forceinline__ void cp16(void* dst, const void* src) {
    asm volatile("cp.async.cg.shared.global [%0], [%1], 16;"
                 :: "r"(smem_u32(dst)), "l"(src));
}
__device__ __forceinline__ void cp_commit() { asm volatile("cp.async.commit_group;"); }
template<int N>
__device__ __forceinline__ void cp_wait() {
    asm volatile("cp.async.wait_group %0;" :: "n"(N));
}
__device__ __forceinline__ void ldm_x4(uint32_t a, uint32_t& r0, uint32_t& r1,
                                       uint32_t& r2, uint32_t& r3) {
    asm volatile("ldmatrix.sync.aligned.m8n8.x4.shared.b16 {%0,%1,%2,%3}, [%4];"
                 : "=r"(r0), "=r"(r1), "=r"(r2), "=r"(r3) : "r"(a));
}
__device__ __forceinline__ void ldm_x4t(uint32_t a, uint32_t& r0, uint32_t& r1,
                                        uint32_t& r2, uint32_t& r3) {
    asm volatile("ldmatrix.sync.aligned.m8n8.x4.trans.shared.b16 {%0,%1,%2,%3}, [%4];"
                 : "=r"(r0), "=r"(r1), "=r"(r2), "=r"(r3) : "r"(a));
}
__device__ __forceinline__ void mma16816(float* c,
                                         uint32_t a0, uint32_t a1, uint32_t a2, uint32_t a3,
                                         uint32_t b0, uint32_t b1) {
    asm volatile("mma.sync.aligned.m16n8k16.row.col.f32.f16.f16.f32 "
                 "{%0,%1,%2,%3}, {%4,%5,%6,%7}, {%8,%9}, {%0,%1,%2,%3};"
                 : "+f"(c[0]), "+f"(c[1]), "+f"(c[2]), "+f"(c[3])
                 : "r"(a0), "r"(a1), "r"(a2), "r"(a3), "r"(b0), "r"(b1));
}
__device__ __forceinline__ uint32_t pack_h2(float x, float y) {
    __half2 t = __floats2half2_rn(x, y);
    return *reinterpret_cast<uint32_t*>(&t);
}

// ------- split-GEMM mainloop: A hi|lo (2-term exact), B hi only -------
__device__ __forceinline__ void gemm_acc(
    const __half* __restrict__ A, const __half* __restrict__ B,
    float acc[2][8][4])
{
    extern __shared__ __half sm[];

    const int row0 = blockIdx.y * 128;
    const int tid  = threadIdx.x;
    const int lane = tid & 31;
    const int warp = tid >> 5;
    const int wm   = warp & 3;
    const int wn   = warp >> 2;

    const int a_row = tid >> 1;
    const int a_sel = tid & 1;
    const int b_row = tid >> 1;
    const int b_half = tid & 1;

    auto load_stage = [&](int c, int stage) {
        __half* As = sm + stage * STAGE_ELEMS;
        __half* Bs = As + 128 * APITCH;
        const size_t gcol = (size_t)a_sel * DIM + c * 32;
        const __half* Ag = A + (size_t)(row0 + a_row) * LK2 + gcol;
        __half* Ad = As + a_row * APITCH + a_sel * 32;
#pragma unroll
        for (int i = 0; i < 4; i++) cp16(Ad + i * 8, Ag + i * 8);
        const __half* Bg = B + (size_t)b_row * DIM + c * 32 + b_half * 16;
        __half* Bd = Bs + b_row * BPITCH + b_half * 16;
#pragma unroll
        for (int i = 0; i < 2; i++) cp16(Bd + i * 8, Bg + i * 8);
        cp_commit();
    };

    const int m_off  = (lane & 7) + ((lane >> 3) & 1) * 8;
    const int k_off  = (lane >> 4) * 8;
    const int n_off  = (lane & 7) + (lane >> 4) * 8;
    const int kb_off = ((lane >> 3) & 1) * 8;

    uint32_t aBase[2], bBase[4];
#pragma unroll
    for (int mi = 0; mi < 2; mi++)
        aBase[mi] = smem_u32(sm + (wm * 32 + mi * 16 + m_off) * APITCH + k_off);
#pragma unroll
    for (int np = 0; np < 4; np++)
        bBase[np] = smem_u32(sm + 128 * APITCH + (wn * 64 + np * 16 + n_off) * BPITCH + kb_off);

#pragma unroll
    for (int i = 0; i < 2; i++)
#pragma unroll
        for (int j = 0; j < 8; j++)
#pragma unroll
            for (int c = 0; c < 4; c++) acc[i][j][c] = 0.f;

    const int nc = DIM / 32;
    load_stage(0, 0);

    for (int c = 0; c < nc; c++) {
        if (c + 1 < nc) load_stage(c + 1, (c + 1) & 1);
        else            cp_commit();
        cp_wait<1>();
        __syncthreads();

        const uint32_t soA = (uint32_t)(c & 1) * STAGE_BYTES;
#pragma unroll
        for (int ks = 0; ks < 2; ks++) {
            uint32_t Ah[2][4], Al[2][4];
#pragma unroll
            for (int mi = 0; mi < 2; mi++) {
                ldm_x4(aBase[mi] + soA + ks * 32,      Ah[mi][0], Ah[mi][1], Ah[mi][2], Ah[mi][3]);
                ldm_x4(aBase[mi] + soA + 64 + ks * 32, Al[mi][0], Al[mi][1], Al[mi][2], Al[mi][3]);
            }
#pragma unroll
            for (int np = 0; np < 4; np++) {
                uint32_t Bh[4];
                ldm_x4(bBase[np] + soA + ks * 32, Bh[0], Bh[1], Bh[2], Bh[3]);
#pragma unroll
                for (int f = 0; f < 2; f++)
#pragma unroll
                    for (int mi = 0; mi < 2; mi++)
                        mma16816(acc[mi][2 * np + f], Ah[mi][0], Ah[mi][1], Ah[mi][2], Ah[mi][3],
                                 Bh[2 * f], Bh[2 * f + 1]);
#pragma unroll
                for (int f = 0; f < 2; f++)
#pragma unroll
                    for (int mi = 0; mi < 2; mi++)
                        mma16816(acc[mi][2 * np + f], Al[mi][0], Al[mi][1], Al[mi][2], Al[mi][3],
                                 Bh[2 * f], Bh[2 * f + 1]);
            }
        }
        __syncthreads();
    }
}

// ---------------- fused QKV ----------------
struct PArgs {
    const __half *Wimg, *Wenc;
    const float* biasEnc;
    const float* nwImg;                 // null for V (no norm)
    const float* nwEnc;
    __half* dst;
    int dstW;                           // 256 (hi|lo) for q, 128 (hi) for k/v
};

__global__ void __launch_bounds__(256, 2)
qkv_fused_k(const __half* __restrict__ Aall, PArgs p0, PArgs p1, PArgs p2,
            const float* __restrict__ rcos, const float* __restrict__ rsin)
{
    PArgs p = (blockIdx.z == 0) ? p0 : (blockIdx.z == 1) ? p1 : p2;
    const int h    = blockIdx.x;
    const int row0 = blockIdx.y * 128;
    const bool enc = row0 < S_TXT;

    const __half* B = (enc ? p.Wenc : p.Wimg) + (size_t)(h * 128) * DIM;

    float acc[2][8][4];
    gemm_acc(Aall, B, acc);

    const int tid  = threadIdx.x;
    const int lane = tid & 31;
    const int warp = tid >> 5;
    const int wm   = warp & 3;
    const int wn   = warp >> 2;
    const int rsel = lane >> 2;
    const int cp2  = (lane & 3) * 2;

    if (enc && p.biasEnc) {
#pragma unroll
        for (int nj = 0; nj < 8; nj++) {
            const int col = h * 128 + wn * 64 + nj * 8 + cp2;
            const float b0 = p.biasEnc[col];
            const float b1 = p.biasEnc[col + 1];
#pragma unroll
            for (int mi = 0; mi < 2; mi++) {
                acc[mi][nj][0] += b0; acc[mi][nj][1] += b1;
                acc[mi][nj][2] += b0; acc[mi][nj][3] += b1;
            }
        }
    }

    const bool doNorm = (p.nwImg != nullptr);
    const bool hiLo   = (p.dstW == 256);

    float inv_r[2][2];
    if (doNorm) {
        extern __shared__ __half sm[];
        float* ss = reinterpret_cast<float*>(sm);
        __syncthreads();
        if (tid < 128) ss[tid] = 0.f;
        __syncthreads();

        float s[2][2] = {{0.f, 0.f}, {0.f, 0.f}};
#pragma unroll
        for (int mi = 0; mi < 2; mi++)
#pragma unroll
            for (int nj = 0; nj < 8; nj++) {
                s[mi][0] += acc[mi][nj][0] * acc[mi][nj][0] + acc[mi][nj][1] * acc[mi][nj][1];
                s[mi][1] += acc[mi][nj][2] * acc[mi][nj][2] + acc[mi][nj][3] * acc[mi][nj][3];
            }
#pragma unroll
        for (int off = 1; off <= 2; off <<= 1) {
            s[0][0] += __shfl_xor_sync(0xffffffffu, s[0][0], off);
            s[0][1] += __shfl_xor_sync(0xffffffffu, s[0][1], off);
            s[1][0] += __shfl_xor_sync(0xffffffffu, s[1][0], off);
            s[1][1] += __shfl_xor_sync(0xffffffffu, s[1][1], off);
        }
        if ((lane & 3) == 0) {
            atomicAdd(&ss[wm * 32 + rsel],          s[0][0]);
            atomicAdd(&ss[wm * 32 + rsel + 8],      s[0][1]);
            atomicAdd(&ss[wm * 32 + 16 + rsel],     s[1][0]);
            atomicAdd(&ss[wm * 32 + 16 + rsel + 8], s[1][1]);
        }
        __syncthreads();
#pragma unroll
        for (int mi = 0; mi < 2; mi++)
#pragma unroll
            for (int half = 0; half < 2; half++) {
                const int lr = wm * 32 + mi * 16 + rsel + half * 8;
                inv_r[mi][half] = rsqrtf(ss[lr] * (1.f / HDIM) + EPS);
            }
    }

    const float* nw = doNorm ? (enc ? p.nwEnc : p.nwImg) : nullptr;
    const int W = p.dstW;
#pragma unroll
    for (int mi = 0; mi < 2; mi++)
#pragma unroll
        for (int half = 0; half < 2; half++) {
            const int lr = wm * 32 + mi * 16 + rsel + half * 8;
            const int srow = row0 + lr;
            __half* base = p.dst + ((size_t)h * S_TOT + srow) * W;
#pragma unroll
            for (int nj = 0; nj < 8; nj++) {
                const int d = wn * 64 + nj * 8 + cp2;
                float o0 = acc[mi][nj][half * 2 + 0];
                float o1 = acc[mi][nj][half * 2 + 1];
                if (doNorm) {
                    const float inv = inv_r[mi][half];
                    const float y0 = o0 * inv * nw[d];
                    const float y1 = o1 * inv * nw[d + 1];
                    const float c0 = rcos[(size_t)srow * HDIM + d];
                    const float c1 = rcos[(size_t)srow * HDIM + d + 1];
                    const float t0 = rsin[(size_t)srow * HDIM + d];
                    const float t1 = rsin[(size_t)srow * HDIM + d + 1];
                    o0 = y0 * c0 - y1 * t0;
                    o1 = y1 * c1 + y0 * t1;
                }
                __half2 hi = __floats2half2_rn(o0, o1);
                *reinterpret_cast<__half2*>(base + d) = hi;
                if (hiLo) {
                    float2 f = __half22float2(hi);
                    __half2 lo = __floats2half2_rn(o0 - f.x, o1 - f.y);
                    *reinterpret_cast<__half2*>(base + 128 + d) = lo;
                }
            }
        }
}

// ---------------- fused output projections ----------------
__global__ void __launch_bounds__(256, 2)
outproj_k(const __half* __restrict__ A,
          const __half* __restrict__ Wo,  const float* __restrict__ bo,
          const __half* __restrict__ Wao, const float* __restrict__ bao,
          float* __restrict__ out)
{
    const int r0 = blockIdx.y * 128;
    const bool encRows = r0 < S_TXT;
    const __half* B = (encRows ? Wao : Wo) + (size_t)(blockIdx.x * 128) * DIM;
    const float* bias = encRows ? bao : bo;
    float* C = encRows ? out + (size_t)S_IMG * DIM : out - (size_t)S_TXT * DIM;

    float acc[2][8][4];
    gemm_acc(A, B, acc);

    const int tid  = threadIdx.x;
    const int lane = tid & 31;
    const int warp = tid >> 5;
    const int wm   = warp & 3;
    const int wn   = warp >> 2;
    const int col0 = blockIdx.x * 128;

#pragma unroll
    for (int mi = 0; mi < 2; mi++) {
#pragma unroll
        for (int nj = 0; nj < 8; nj++) {
            const int row = r0 + wm * 32 + mi * 16 + (lane >> 2);
            const int col = col0 + wn * 64 + nj * 8 + (lane & 3) * 2;
            const float b0 = bias[col];
            const float b1 = bias[col + 1];
            float2 v0 = { acc[mi][nj][0] + b0, acc[mi][nj][1] + b1 };
            float2 v1 = { acc[mi][nj][2] + b0, acc[mi][nj][3] + b1 };
            *reinterpret_cast<float2*>(&C[(size_t)row * DIM + col])       = v0;
            *reinterpret_cast<float2*>(&C[(size_t)(row + 8) * DIM + col]) = v1;
        }
    }
}

// ---------------- converts ----------------
__global__ void __launch_bounds__(256)
conv_hl_k(const float* __restrict__ in, __half* __restrict__ out, int M, int rowOff)
{
    const int idx = blockIdx.x * 256 + threadIdx.x;
    const int tot = M * (DIM / 4);
    if (idx >= tot) return;
    const int m = idx / (DIM / 4);
    const int c = (idx % (DIM / 4)) * 4;
    float4 v = *reinterpret_cast<const float4*>(in + (size_t)m * DIM + c);
    h4 hi, lo;
    split4h(v, hi, lo);
    __half* base = out + (size_t)(rowOff + m) * LK2 + c;
    *reinterpret_cast<h4*>(base)       = hi;
    *reinterpret_cast<h4*>(base + DIM) = lo;
}

struct W8 { const float* p[8]; };
__global__ void __launch_bounds__(256)
conv_w8_k(W8 w, __half* __restrict__ out)
{
    const float* in = w.p[blockIdx.z];
    __half* o = out + (size_t)blockIdx.z * DIM * DIM;
    const int idx = blockIdx.x * 256 + threadIdx.x;
    if (idx >= DIM * (DIM / 4)) return;
    const int m = idx / (DIM / 4);
    const int c = (idx % (DIM / 4)) * 4;
    float4 v = *reinterpret_cast<const float4*>(in + (size_t)m * DIM + c);
    h4 hi, lo;
    split4h(v, hi, lo);
    *reinterpret_cast<h4*>(o + (size_t)m * DIM + c) = hi;   // hi only
}

// ---------------- flash attention: fp16, K/V hi-only ----------------
__global__ void __launch_bounds__(128, 2)
flash_k(const __half* __restrict__ qg, const __half* __restrict__ kg,
        const __half* __restrict__ vg, __half* __restrict__ ocat)
{
    extern __shared__ __half sm[];
    const int h  = blockIdx.y;
    const int q0 = blockIdx.x * FQ;
    const int tid  = threadIdx.x;
    const int lane = tid & 31;
    const int warp = tid >> 5;

    const __half* qh_base = qg + ((size_t)h * S_TOT + q0) * 256;
    const __half* kh_base = kg + (size_t)h * S_TOT * 128;
    const __half* vh_base = vg + (size_t)h * S_TOT * 128;

    __half* Qs  = sm;                   // [FQ][QP]
    __half* KV0 = sm + FQ * QP;         // stage st: K [FKV][KP] then V [FKV][KP]

#pragma unroll
    for (int i = 0; i < 16; i++) {
        int idx = tid + i * 128;
        int r = idx >> 5, cc = (idx & 31) * 8;
        cp16(Qs + r * QP + cc, qh_base + (size_t)r * 256 + cc);
    }

    auto loadKV = [&](int it, int st) {
        __half* Ks = KV0 + st * FL_STAGE_E;
        __half* Vs = Ks + FKV * KP;
        const __half* kb = kh_base + (size_t)(it * FKV) * 128;
        const __half* vb = vh_base + (size_t)(it * FKV) * 128;
#pragma unroll
        for (int i = 0; i < 4; i++) {
            int idx = tid + i * 128;
            int r = idx >> 4, cc = (idx & 15) * 8;
            cp16(Ks + r * KP + cc, kb + (size_t)r * 128 + cc);
        }
#pragma unroll
        for (int i = 0; i < 4; i++) {
            int idx = tid + i * 128;
            int r = idx >> 4, cc = (idx & 15) * 8;
            cp16(Vs + r * KP + cc, vb + (size_t)r * 128 + cc);
        }
        cp_commit();
    };

    loadKV(0, 0);
    loadKV(1, 1);

    const int m_off  = (lane & 7) + ((lane >> 3) & 1) * 8;
    const int k_off  = (lane >> 4) * 8;
    const int n_off  = (lane & 7) + (lane >> 4) * 8;
    const int kb_off = ((lane >> 3) & 1) * 8;
    const int t_krow = (lane & 7) + ((lane >> 3) & 1) * 8;
    const int t_noff = (lane >> 4) * 8;

    const uint32_t aQ = smem_u32(Qs + (warp * 16 + m_off) * QP + k_off);
    uint32_t kB[2], vB[8];
#pragma unroll
    for (int np = 0; np < 2; np++)
        kB[np] = smem_u32(KV0 + (np * 16 + n_off) * KP + kb_off);
#pragma unroll
    for (int np = 0; np < 8; np++)
        vB[np] = smem_u32(KV0 + FKV * KP + t_krow * KP + np * 16 + t_noff);

    uint32_t qhf[8][4], qlf[8][4];
    float oAcc[16][4];
#pragma unroll
    for (int j = 0; j < 16; j++)
#pragma unroll
        for (int c = 0; c < 4; c++) oAcc[j][c] = 0.f;
    float mrow[2] = { -1e30f, -1e30f };
    float lrow[2] = { 0.f, 0.f };

    for (int it = 0; it < NKV; it++) {
        cp_wait<1>();
        __syncthreads();

        if (it == 0) {
#pragma unroll
            for (int ks = 0; ks < 8; ks++) {
                ldm_x4(aQ + ks * 32,       qhf[ks][0], qhf[ks][1], qhf[ks][2], qhf[ks][3]);
                ldm_x4(aQ + 256 + ks * 32, qlf[ks][0], qlf[ks][1], qlf[ks][2], qlf[ks][3]);
            }
        }

        const uint32_t so = (uint32_t)(it & 1) * FL_STAGE_B;

        float sAcc[4][4];
#pragma unroll
        for (int j = 0; j < 4; j++)
#pragma unroll
            for (int c = 0; c < 4; c++) sAcc[j][c] = 0.f;

        // ---- QK: 2 terms (Qh·Kh + Ql·Kh)
#pragma unroll
        for (int ks = 0; ks < 8; ks++) {
            uint32_t kh[2][4];
#pragma unroll
            for (int np = 0; np < 2; np++)
                ldm_x4(kB[np] + so + ks * 32, kh[np][0], kh[np][1], kh[np][2], kh[np][3]);
#pragma unroll
            for (int np = 0; np < 2; np++)
#pragma unroll
                for (int f = 0; f < 2; f++)
                    mma16816(sAcc[2 * np + f], qhf[ks][0], qhf[ks][1], qhf[ks][2], qhf[ks][3],
                             kh[np][2 * f], kh[np][2 * f + 1]);
#pragma unroll
            for (int np = 0; np < 2; np++)
#pragma unroll
                for (int f = 0; f < 2; f++)
                    mma16816(sAcc[2 * np + f], qlf[ks][0], qlf[ks][1], qlf[ks][2], qlf[ks][3],
                             kh[np][2 * f], kh[np][2 * f + 1]);
        }

        float rmax0 = -1e30f, rmax1 = -1e30f;
#pragma unroll
        for (int f = 0; f < 4; f++) {
            rmax0 = fmaxf(rmax0, fmaxf(sAcc[f][0], sAcc[f][1]));
            rmax1 = fmaxf(rmax1, fmaxf(sAcc[f][2], sAcc[f][3]));
        }
#pragma unroll
        for (int off = 1; off <= 2; off <<= 1) {
            rmax0 = fmaxf(rmax0, __shfl_xor_sync(0xffffffffu, rmax0, off));
            rmax1 = fmaxf(rmax1, __shfl_xor_sync(0xffffffffu, rmax1, off));
        }
        float mnew0 = fmaxf(mrow[0], rmax0);
        float mnew1 = fmaxf(mrow[1], rmax1);
        float cf0 = exp2f((mrow[0] - mnew0) * C2EXP);
        float cf1 = exp2f((mrow[1] - mnew1) * C2EXP);
        mrow[0] = mnew0; mrow[1] = mnew1;

#pragma unroll
        for (int j = 0; j < 16; j++) {
            oAcc[j][0] *= cf0; oAcc[j][1] *= cf0;
            oAcc[j][2] *= cf1; oAcc[j][3] *= cf1;
        }

        float sum0 = 0.f, sum1 = 0.f;
        uint32_t ph[2][4], pl[2][4];
#pragma unroll
        for (int ks = 0; ks < 2; ks++) {
            float p[8];
#pragma unroll
            for (int f = 0; f < 2; f++) {
                float* s = sAcc[2 * ks + f];
                p[4 * f + 0] = exp2f((s[0] - mnew0) * C2EXP);
                p[4 * f + 1] = exp2f((s[1] - mnew0) * C2EXP);
                p[4 * f + 2] = exp2f((s[2] - mnew1) * C2EXP);
                p[4 * f + 3] = exp2f((s[3] - mnew1) * C2EXP);
            }
            sum0 += p[0] + p[1] + p[4] + p[5];
            sum1 += p[2] + p[3] + p[6] + p[7];
            ph[ks][0] = pack_h2(p[0], p[1]);
            ph[ks][1] = pack_h2(p[2], p[3]);
            ph[ks][2] = pack_h2(p[4], p[5]);
            ph[ks][3] = pack_h2(p[6], p[7]);
            __half2 t0 = __floats2half2_rn(p[0], p[1]);
            __half2 t1 = __floats2half2_rn(p[2], p[3]);
            __half2 t2 = __floats2half2_rn(p[4], p[5]);
            __half2 t3 = __floats2half2_rn(p[6], p[7]);
            float2 g0 = __half22float2(t0), g1 = __half22float2(t1);
            float2 g2 = __half22float2(t2), g3 = __half22float2(t3);
            pl[ks][0] = pack_h2(p[0] - g0.x, p[1] - g0.y);
            pl[ks][1] = pack_h2(p[2] - g1.x, p[3] - g1.y);
            pl[ks][2] = pack_h2(p[4] - g2.x, p[5] - g2.y);
            pl[ks][3] = pack_h2(p[6] - g3.x, p[7] - g3.y);
        }
#pragma unroll
        for (int off = 1; off <= 2; off <<= 1) {
            sum0 += __shfl_xor_sync(0xffffffffu, sum0, off);
            sum1 += __shfl_xor_sync(0xffffffffu, sum1, off);
        }
        lrow[0] = lrow[0] * cf0 + sum0;
        lrow[1] = lrow[1] * cf1 + sum1;

        // ---- PV: 2 terms (Ph·Vh + Pl·Vh)
#pragma unroll
        for (int ks = 0; ks < 2; ks++) {
            const uint32_t vo = so + ks * (16 * KP * 2);
#pragma unroll
            for (int np = 0; np < 8; np++) {
                uint32_t vh[4];
                ldm_x4t(vB[np] + vo, vh[0], vh[1], vh[2], vh[3]);
#pragma unroll
                for (int f = 0; f < 2; f++)
                    mma16816(oAcc[2 * np + f], ph[ks][0], ph[ks][1], ph[ks][2], ph[ks][3],
                             vh[2 * f], vh[2 * f + 1]);
#pragma unroll
                for (int f = 0; f < 2; f++)
                    mma16816(oAcc[2 * np + f], pl[ks][0], pl[ks][1], pl[ks][2], pl[ks][3],
                             vh[2 * f], vh[2 * f + 1]);
            }
        }

        __syncthreads();
        if (it + 2 < NKV) loadKV(it + 2, it & 1);
        else              cp_commit();
    }

    const float inv0 = 1.f / lrow[0];
    const float inv1 = 1.f / lrow[1];
    const int r0 = q0 + warp * 16 + (lane >> 2);
    const int colb = (lane & 3) * 2;
#pragma unroll
    for (int nj = 0; nj < 16; nj++) {
        const int col = h * HDIM + nj * 8 + colb;
        float o0 = oAcc[nj][0] * inv0, o1 = oAcc[nj][1] * inv0;
        float o2 = oAcc[nj][2] * inv1, o3 = oAcc[nj][3] * inv1;
        __half2 h01 = __floats2half2_rn(o0, o1);
        __half2 h23 = __floats2half2_rn(o2, o3);
        float2 f01 = __half22float2(h01);
        float2 f23 = __half22float2(h23);
        __half2 l01 = __floats2half2_rn(o0 - f01.x, o1 - f01.y);
        __half2 l23 = __floats2half2_rn(o2 - f23.x, o3 - f23.y);
        __half* b0 = ocat + (size_t)r0 * LK2 + col;
        __half* b1 = ocat + (size_t)(r0 + 8) * LK2 + col;
        *reinterpret_cast<__half2*>(b0)        = h01;
        *reinterpret_cast<__half2*>(b0 + DIM)  = l01;
        *reinterpret_cast<__half2*>(b1)        = h23;
        *reinterpret_cast<__half2*>(b1 + DIM)  = l23;
    }
}

// ---------------- launch ----------------
extern "C" void kernel_launch(void* const* d_in, const int* in_sizes, int n_in,
                              void* d_out, int out_size)
{
    (void)in_sizes; (void)n_in; (void)out_size;
    const float* x    = (const float*)d_in[0];
    const float* ehs  = (const float*)d_in[1];
    const float* rcos = (const float*)d_in[2];
    const float* rsin = (const float*)d_in[3];
    W8 w8 = {{ (const float*)d_in[4],  (const float*)d_in[5],
               (const float*)d_in[6],  (const float*)d_in[7],
               (const float*)d_in[8],  (const float*)d_in[9],
               (const float*)d_in[17], (const float*)d_in[19] }};
    const float* baq  = (const float*)d_in[10];
    const float* bak  = (const float*)d_in[11];
    const float* bav  = (const float*)d_in[12];
    const float* nqw  = (const float*)d_in[13];
    const float* nkw  = (const float*)d_in[14];
    const float* naqw = (const float*)d_in[15];
    const float* nakw = (const float*)d_in[16];
    const float* bo   = (const float*)d_in[18];
    const float* bao  = (const float*)d_in[20];
    float* out = (float*)d_out;

    __half *acat, *qg, *kg, *vg, *ocat, *wcat;
    cudaGetSymbolAddress((void**)&acat, g_acat);
    cudaGetSymbolAddress((void**)&qg,   g_qg);
    cudaGetSymbolAddress((void**)&kg,   g_kg);
    cudaGetSymbolAddress((void**)&vg,   g_vg);
    cudaGetSymbolAddress((void**)&ocat, g_ocat);
    cudaGetSymbolAddress((void**)&wcat, g_wcat);

    cudaFuncSetAttribute(qkv_fused_k, cudaFuncAttributeMaxDynamicSharedMemorySize, SMEM_BYTES);
    cudaFuncSetAttribute(outproj_k,   cudaFuncAttributeMaxDynamicSharedMemorySize, SMEM_BYTES);
    cudaFuncSetAttribute(flash_k,     cudaFuncAttributeMaxDynamicSharedMemorySize, FL_SMEM);

    const dim3 blk(256);
    const size_t WSTRIDE = (size_t)DIM * DIM;

    conv_hl_k<<<dim3((S_TXT * DIM / 4 + 255) / 256), blk>>>(ehs, acat, S_TXT, 0);
    conv_hl_k<<<dim3((S_IMG * DIM / 4 + 255) / 256), blk>>>(x,   acat, S_IMG, S_TXT);
    conv_w8_k<<<dim3((DIM * DIM / 4 + 255) / 256, 1, 8), blk>>>(w8, wcat);

    {
        PArgs pq = { wcat + 0 * WSTRIDE, wcat + 3 * WSTRIDE, baq, nqw, naqw, qg, 256 };
        PArgs pk = { wcat + 1 * WSTRIDE, wcat + 4 * WSTRIDE, bak, nkw, nakw, kg, 128 };
        PArgs pv = { wcat + 2 * WSTRIDE, wcat + 5 * WSTRIDE, bav, nullptr, nullptr, vg, 128 };
        qkv_fused_k<<<dim3(HEADS, S_TOT / 128, 3), blk, SMEM_BYTES>>>(
            acat, pq, pk, pv, rcos, rsin);
    }

    flash_k<<<dim3(S_TOT / FQ, HEADS), dim3(128), FL_SMEM>>>(qg, kg, vg, ocat);

    outproj_k<<<dim3(DIM / 128, S_TOT / 128), blk, SMEM_BYTES>>>(
        ocat, wcat + 6 * WSTRIDE, bo, wcat + 7 * WSTRIDE, bao, out);
}

// round 17
// speedup vs baseline: 1.5983x; 1.0367x over previous
#include <cuda_runtime.h>
#include <cuda_fp16.h>
#include <math.h>
#include <stdint.h>

// ---------------- problem constants ----------------
#define HEADS   24
#define HDIM    128
#define DIM     3072
#define S_TXT   512
#define S_IMG   2048
#define S_TOT   2560
#define EPS     1e-5f
#define QK_SCALE 0.08838834764831845f
#define C2EXP   (QK_SCALE * 1.44269504088896f)

#define LK2         6144            // 2*DIM : [hi|lo] packed A-side K
#define APITCH      72
#define BPITCH      40
#define STAGE_ELEMS (128 * APITCH + 128 * BPITCH)   // 14336
#define STAGE_BYTES (STAGE_ELEMS * 2)               // 28672
#define SMEM_BYTES  (2 * STAGE_BYTES)               // 57344 -> 2 CTAs/SM

// flash tiling: Q 64 (hi|lo), KV 64 x 128 (hi only)
#define QP          264
#define KP          136
#define FQ          64
#define FKV         64
#define FL_STAGE_E  (2 * FKV * KP)                  // 17408 elems
#define FL_STAGE_B  (FL_STAGE_E * 2)                // 34816 B
#define FL_SMEM     ((FQ * QP + 2 * FL_STAGE_E) * 2)  // 103424 B -> 2 CTAs/SM
#define NKV         (S_TOT / FKV)                   // 40

// ---------------- scratch ----------------
__device__ __half  g_acat[(size_t)S_TOT * LK2];
__device__ __half  g_qg[(size_t)HEADS * S_TOT * 256];   // hi|lo
__device__ __half  g_kg[(size_t)HEADS * S_TOT * 128];   // hi only
__device__ __half  g_vg[(size_t)HEADS * S_TOT * 128];   // hi only
__device__ __half  g_ocat[(size_t)S_TOT * LK2];
__device__ __half  g_wcat[8][(size_t)DIM * DIM];        // hi only

// ---------------- helpers ----------------
struct h4 { __half2 a, b; };

__device__ __forceinline__ void split4h(float4 v, h4& hi, h4& lo) {
    __half2 h01 = __floats2half2_rn(v.x, v.y);
    __half2 h23 = __floats2half2_rn(v.z, v.w);
    float2 f01 = __half22float2(h01);
    float2 f23 = __half22float2(h23);
    hi.a = h01; hi.b = h23;
    lo.a = __floats2half2_rn(v.x - f01.x, v.y - f01.y);
    lo.b = __floats2half2_rn(v.z - f23.x, v.w - f23.y);
}
__device__ __forceinline__ uint32_t smem_u32(const void* p) {
    return static_cast<uint32_t>(__cvta_generic_to_shared(p));
}
__device__ __forceinline__ void cp16(void* dst, const void* src) {
    asm volatile("cp.async.cg.shared.global [%0], [%1], 16;"
                 :: "r"(smem_u32(dst)), "l"(src));
}
__device__ __forceinline__ void cp_commit() { asm volatile("cp.async.commit_group;"); }
template<int N>
__device__ __forceinline__ void cp_wait() {
    asm volatile("cp.async.wait_group %0;" :: "n"(N));
}
__device__ __forceinline__ void ldm_x4(uint32_t a, uint32_t& r0, uint32_t& r1,
                                       uint32_t& r2, uint32_t& r3) {
    asm volatile("ldmatrix.sync.aligned.m8n8.x4.shared.b16 {%0,%1,%2,%3}, [%4];"
                 : "=r"(r0), "=r"(r1), "=r"(r2), "=r"(r3) : "r"(a));
}
__device__ __forceinline__ void ldm_x4t(uint32_t a, uint32_t& r0, uint32_t& r1,
                                        uint32_t& r2, uint32_t& r3) {
    asm volatile("ldmatrix.sync.aligned.m8n8.x4.trans.shared.b16 {%0,%1,%2,%3}, [%4];"
                 : "=r"(r0), "=r"(r1), "=r"(r2), "=r"(r3) : "r"(a));
}
__device__ __forceinline__ void mma16816(float* c,
                                         uint32_t a0, uint32_t a1, uint32_t a2, uint32_t a3,
                                         uint32_t b0, uint32_t b1) {
    asm volatile("mma.sync.aligned.m16n8k16.row.col.f32.f16.f16.f32 "
                 "{%0,%1,%2,%3}, {%4,%5,%6,%7}, {%8,%9}, {%0,%1,%2,%3};"
                 : "+f"(c[0]), "+f"(c[1]), "+f"(c[2]), "+f"(c[3])
                 : "r"(a0), "r"(a1), "r"(a2), "r"(a3), "r"(b0), "r"(b1));
}
__device__ __forceinline__ uint32_t pack_h2(float x, float y) {
    __half2 t = __floats2half2_rn(x, y);
    return *reinterpret_cast<uint32_t*>(&t);
}

// ------- split-GEMM mainloop: A hi|lo (2-term), B hi only -------
__device__ __forceinline__ void gemm_acc(
    const __half* __restrict__ A, const __half* __restrict__ B,
    float acc[2][8][4])
{
    extern __shared__ __half sm[];

    const int row0 = blockIdx.y * 128;
    const int tid  = threadIdx.x;
    const int lane = tid & 31;
    const int warp = tid >> 5;
    const int wm   = warp & 3;
    const int wn   = warp >> 2;

    const int a_row = tid >> 1;
    const int a_sel = tid & 1;
    const int b_row = tid >> 1;
    const int b_half = tid & 1;

    auto load_stage = [&](int c, int stage) {
        __half* As = sm + stage * STAGE_ELEMS;
        __half* Bs = As + 128 * APITCH;
        const size_t gcol = (size_t)a_sel * DIM + c * 32;
        const __half* Ag = A + (size_t)(row0 + a_row) * LK2 + gcol;
        __half* Ad = As + a_row * APITCH + a_sel * 32;
#pragma unroll
        for (int i = 0; i < 4; i++) cp16(Ad + i * 8, Ag + i * 8);
        const __half* Bg = B + (size_t)b_row * DIM + c * 32 + b_half * 16;
        __half* Bd = Bs + b_row * BPITCH + b_half * 16;
#pragma unroll
        for (int i = 0; i < 2; i++) cp16(Bd + i * 8, Bg + i * 8);
        cp_commit();
    };

    const int m_off  = (lane & 7) + ((lane >> 3) & 1) * 8;
    const int k_off  = (lane >> 4) * 8;
    const int n_off  = (lane & 7) + (lane >> 4) * 8;
    const int kb_off = ((lane >> 3) & 1) * 8;

    uint32_t aBase[2], bBase[4];
#pragma unroll
    for (int mi = 0; mi < 2; mi++)
        aBase[mi] = smem_u32(sm + (wm * 32 + mi * 16 + m_off) * APITCH + k_off);
#pragma unroll
    for (int np = 0; np < 4; np++)
        bBase[np] = smem_u32(sm + 128 * APITCH + (wn * 64 + np * 16 + n_off) * BPITCH + kb_off);

#pragma unroll
    for (int i = 0; i < 2; i++)
#pragma unroll
        for (int j = 0; j < 8; j++)
#pragma unroll
            for (int c = 0; c < 4; c++) acc[i][j][c] = 0.f;

    const int nc = DIM / 32;
    load_stage(0, 0);

    for (int c = 0; c < nc; c++) {
        if (c + 1 < nc) load_stage(c + 1, (c + 1) & 1);
        else            cp_commit();
        cp_wait<1>();
        __syncthreads();

        const uint32_t soA = (uint32_t)(c & 1) * STAGE_BYTES;
#pragma unroll
        for (int ks = 0; ks < 2; ks++) {
            uint32_t Ah[2][4], Al[2][4];
#pragma unroll
            for (int mi = 0; mi < 2; mi++) {
                ldm_x4(aBase[mi] + soA + ks * 32,      Ah[mi][0], Ah[mi][1], Ah[mi][2], Ah[mi][3]);
                ldm_x4(aBase[mi] + soA + 64 + ks * 32, Al[mi][0], Al[mi][1], Al[mi][2], Al[mi][3]);
            }
#pragma unroll
            for (int np = 0; np < 4; np++) {
                uint32_t Bh[4];
                ldm_x4(bBase[np] + soA + ks * 32, Bh[0], Bh[1], Bh[2], Bh[3]);
#pragma unroll
                for (int f = 0; f < 2; f++)
#pragma unroll
                    for (int mi = 0; mi < 2; mi++)
                        mma16816(acc[mi][2 * np + f], Ah[mi][0], Ah[mi][1], Ah[mi][2], Ah[mi][3],
                                 Bh[2 * f], Bh[2 * f + 1]);
#pragma unroll
                for (int f = 0; f < 2; f++)
#pragma unroll
                    for (int mi = 0; mi < 2; mi++)
                        mma16816(acc[mi][2 * np + f], Al[mi][0], Al[mi][1], Al[mi][2], Al[mi][3],
                                 Bh[2 * f], Bh[2 * f + 1]);
            }
        }
        __syncthreads();
    }
}

// ---------------- fused QKV ----------------
struct PArgs {
    const __half *Wimg, *Wenc;
    const float* biasEnc;
    const float* nwImg;                 // null for V (no norm)
    const float* nwEnc;
    __half* dst;
    int dstW;                           // 256 (hi|lo) for q, 128 (hi) for k/v
};

__global__ void __launch_bounds__(256, 2)
qkv_fused_k(const __half* __restrict__ Aall, PArgs p0, PArgs p1, PArgs p2,
            const float* __restrict__ rcos, const float* __restrict__ rsin)
{
    PArgs p = (blockIdx.z == 0) ? p0 : (blockIdx.z == 1) ? p1 : p2;
    const int h    = blockIdx.x;
    const int row0 = blockIdx.y * 128;
    const bool enc = row0 < S_TXT;

    const __half* B = (enc ? p.Wenc : p.Wimg) + (size_t)(h * 128) * DIM;

    float acc[2][8][4];
    gemm_acc(Aall, B, acc);

    const int tid  = threadIdx.x;
    const int lane = tid & 31;
    const int warp = tid >> 5;
    const int wm   = warp & 3;
    const int wn   = warp >> 2;
    const int rsel = lane >> 2;
    const int cp2  = (lane & 3) * 2;

    if (enc && p.biasEnc) {
#pragma unroll
        for (int nj = 0; nj < 8; nj++) {
            const int col = h * 128 + wn * 64 + nj * 8 + cp2;
            const float b0 = p.biasEnc[col];
            const float b1 = p.biasEnc[col + 1];
#pragma unroll
            for (int mi = 0; mi < 2; mi++) {
                acc[mi][nj][0] += b0; acc[mi][nj][1] += b1;
                acc[mi][nj][2] += b0; acc[mi][nj][3] += b1;
            }
        }
    }

    const bool doNorm = (p.nwImg != nullptr);
    const bool hiLo   = (p.dstW == 256);

    float inv_r[2][2];
    if (doNorm) {
        extern __shared__ __half sm[];
        float* ss = reinterpret_cast<float*>(sm);
        __syncthreads();
        if (tid < 128) ss[tid] = 0.f;
        __syncthreads();

        float s[2][2] = {{0.f, 0.f}, {0.f, 0.f}};
#pragma unroll
        for (int mi = 0; mi < 2; mi++)
#pragma unroll
            for (int nj = 0; nj < 8; nj++) {
                s[mi][0] += acc[mi][nj][0] * acc[mi][nj][0] + acc[mi][nj][1] * acc[mi][nj][1];
                s[mi][1] += acc[mi][nj][2] * acc[mi][nj][2] + acc[mi][nj][3] * acc[mi][nj][3];
            }
#pragma unroll
        for (int off = 1; off <= 2; off <<= 1) {
            s[0][0] += __shfl_xor_sync(0xffffffffu, s[0][0], off);
            s[0][1] += __shfl_xor_sync(0xffffffffu, s[0][1], off);
            s[1][0] += __shfl_xor_sync(0xffffffffu, s[1][0], off);
            s[1][1] += __shfl_xor_sync(0xffffffffu, s[1][1], off);
        }
        if ((lane & 3) == 0) {
            atomicAdd(&ss[wm * 32 + rsel],          s[0][0]);
            atomicAdd(&ss[wm * 32 + rsel + 8],      s[0][1]);
            atomicAdd(&ss[wm * 32 + 16 + rsel],     s[1][0]);
            atomicAdd(&ss[wm * 32 + 16 + rsel + 8], s[1][1]);
        }
        __syncthreads();
#pragma unroll
        for (int mi = 0; mi < 2; mi++)
#pragma unroll
            for (int half = 0; half < 2; half++) {
                const int lr = wm * 32 + mi * 16 + rsel + half * 8;
                inv_r[mi][half] = rsqrtf(ss[lr] * (1.f / HDIM) + EPS);
            }
    }

    const float* nw = doNorm ? (enc ? p.nwEnc : p.nwImg) : nullptr;
    const int W = p.dstW;
#pragma unroll
    for (int mi = 0; mi < 2; mi++)
#pragma unroll
        for (int half = 0; half < 2; half++) {
            const int lr = wm * 32 + mi * 16 + rsel + half * 8;
            const int srow = row0 + lr;
            __half* base = p.dst + ((size_t)h * S_TOT + srow) * W;
#pragma unroll
            for (int nj = 0; nj < 8; nj++) {
                const int d = wn * 64 + nj * 8 + cp2;
                float o0 = acc[mi][nj][half * 2 + 0];
                float o1 = acc[mi][nj][half * 2 + 1];
                if (doNorm) {
                    const float inv = inv_r[mi][half];
                    const float y0 = o0 * inv * nw[d];
                    const float y1 = o1 * inv * nw[d + 1];
                    const float c0 = rcos[(size_t)srow * HDIM + d];
                    const float c1 = rcos[(size_t)srow * HDIM + d + 1];
                    const float t0 = rsin[(size_t)srow * HDIM + d];
                    const float t1 = rsin[(size_t)srow * HDIM + d + 1];
                    o0 = y0 * c0 - y1 * t0;
                    o1 = y1 * c1 + y0 * t1;
                }
                __half2 hi = __floats2half2_rn(o0, o1);
                *reinterpret_cast<__half2*>(base + d) = hi;
                if (hiLo) {
                    float2 f = __half22float2(hi);
                    __half2 lo = __floats2half2_rn(o0 - f.x, o1 - f.y);
                    *reinterpret_cast<__half2*>(base + 128 + d) = lo;
                }
            }
        }
}

// ---------------- fused output projections ----------------
__global__ void __launch_bounds__(256, 2)
outproj_k(const __half* __restrict__ A,
          const __half* __restrict__ Wo,  const float* __restrict__ bo,
          const __half* __restrict__ Wao, const float* __restrict__ bao,
          float* __restrict__ out)
{
    const int r0 = blockIdx.y * 128;
    const bool encRows = r0 < S_TXT;
    const __half* B = (encRows ? Wao : Wo) + (size_t)(blockIdx.x * 128) * DIM;
    const float* bias = encRows ? bao : bo;
    float* C = encRows ? out + (size_t)S_IMG * DIM : out - (size_t)S_TXT * DIM;

    float acc[2][8][4];
    gemm_acc(A, B, acc);

    const int tid  = threadIdx.x;
    const int lane = tid & 31;
    const int warp = tid >> 5;
    const int wm   = warp & 3;
    const int wn   = warp >> 2;
    const int col0 = blockIdx.x * 128;

#pragma unroll
    for (int mi = 0; mi < 2; mi++) {
#pragma unroll
        for (int nj = 0; nj < 8; nj++) {
            const int row = r0 + wm * 32 + mi * 16 + (lane >> 2);
            const int col = col0 + wn * 64 + nj * 8 + (lane & 3) * 2;
            const float b0 = bias[col];
            const float b1 = bias[col + 1];
            float2 v0 = { acc[mi][nj][0] + b0, acc[mi][nj][1] + b1 };
            float2 v1 = { acc[mi][nj][2] + b0, acc[mi][nj][3] + b1 };
            *reinterpret_cast<float2*>(&C[(size_t)row * DIM + col])       = v0;
            *reinterpret_cast<float2*>(&C[(size_t)(row + 8) * DIM + col]) = v1;
        }
    }
}

// ---------------- converts ----------------
__global__ void __launch_bounds__(256)
conv_hl_k(const float* __restrict__ in, __half* __restrict__ out, int M, int rowOff)
{
    const int idx = blockIdx.x * 256 + threadIdx.x;
    const int tot = M * (DIM / 4);
    if (idx >= tot) return;
    const int m = idx / (DIM / 4);
    const int c = (idx % (DIM / 4)) * 4;
    float4 v = *reinterpret_cast<const float4*>(in + (size_t)m * DIM + c);
    h4 hi, lo;
    split4h(v, hi, lo);
    __half* base = out + (size_t)(rowOff + m) * LK2 + c;
    *reinterpret_cast<h4*>(base)       = hi;
    *reinterpret_cast<h4*>(base + DIM) = lo;
}

struct W8 { const float* p[8]; };
__global__ void __launch_bounds__(256)
conv_w8_k(W8 w, __half* __restrict__ out)
{
    const float* in = w.p[blockIdx.z];
    __half* o = out + (size_t)blockIdx.z * DIM * DIM;
    const int idx = blockIdx.x * 256 + threadIdx.x;
    if (idx >= DIM * (DIM / 4)) return;
    const int m = idx / (DIM / 4);
    const int c = (idx % (DIM / 4)) * 4;
    float4 v = *reinterpret_cast<const float4*>(in + (size_t)m * DIM + c);
    h4 hi, lo;
    split4h(v, hi, lo);
    *reinterpret_cast<h4*>(o + (size_t)m * DIM + c) = hi;
}

// ---------------- flash attention: fp16, KV tile 64, P single-term ----------------
__global__ void __launch_bounds__(128, 2)
flash_k(const __half* __restrict__ qg, const __half* __restrict__ kg,
        const __half* __restrict__ vg, __half* __restrict__ ocat)
{
    extern __shared__ __half sm[];
    const int h  = blockIdx.y;
    const int q0 = blockIdx.x * FQ;
    const int tid  = threadIdx.x;
    const int lane = tid & 31;
    const int warp = tid >> 5;

    const __half* qh_base = qg + ((size_t)h * S_TOT + q0) * 256;
    const __half* kh_base = kg + (size_t)h * S_TOT * 128;
    const __half* vh_base = vg + (size_t)h * S_TOT * 128;

    __half* Qs  = sm;                   // [FQ][QP]
    __half* KV0 = sm + FQ * QP;         // stage st: K [FKV][KP] then V [FKV][KP]

#pragma unroll
    for (int i = 0; i < 16; i++) {
        int idx = tid + i * 128;
        int r = idx >> 5, cc = (idx & 31) * 8;
        cp16(Qs + r * QP + cc, qh_base + (size_t)r * 256 + cc);
    }

    auto loadKV = [&](int it, int st) {
        __half* Ks = KV0 + st * FL_STAGE_E;
        __half* Vs = Ks + FKV * KP;
        const __half* kb = kh_base + (size_t)(it * FKV) * 128;
        const __half* vb = vh_base + (size_t)(it * FKV) * 128;
#pragma unroll
        for (int i = 0; i < 8; i++) {
            int idx = tid + i * 128;
            int r = idx >> 4, cc = (idx & 15) * 8;
            cp16(Ks + r * KP + cc, kb + (size_t)r * 128 + cc);
        }
#pragma unroll
        for (int i = 0; i < 8; i++) {
            int idx = tid + i * 128;
            int r = idx >> 4, cc = (idx & 15) * 8;
            cp16(Vs + r * KP + cc, vb + (size_t)r * 128 + cc);
        }
        cp_commit();
    };

    loadKV(0, 0);
    loadKV(1, 1);

    const int m_off  = (lane & 7) + ((lane >> 3) & 1) * 8;
    const int k_off  = (lane >> 4) * 8;
    const int n_off  = (lane & 7) + (lane >> 4) * 8;
    const int kb_off = ((lane >> 3) & 1) * 8;
    const int t_krow = (lane & 7) + ((lane >> 3) & 1) * 8;
    const int t_noff = (lane >> 4) * 8;

    const uint32_t aQ = smem_u32(Qs + (warp * 16 + m_off) * QP + k_off);
    uint32_t kB[4], vB[8];
#pragma unroll
    for (int np = 0; np < 4; np++)
        kB[np] = smem_u32(KV0 + (np * 16 + n_off) * KP + kb_off);
#pragma unroll
    for (int np = 0; np < 8; np++)
        vB[np] = smem_u32(KV0 + FKV * KP + t_krow * KP + np * 16 + t_noff);

    uint32_t qhf[8][4], qlf[8][4];
    float oAcc[16][4];
#pragma unroll
    for (int j = 0; j < 16; j++)
#pragma unroll
        for (int c = 0; c < 4; c++) oAcc[j][c] = 0.f;
    float mrow[2] = { -1e30f, -1e30f };
    float lrow[2] = { 0.f, 0.f };

    for (int it = 0; it < NKV; it++) {
        cp_wait<1>();
        __syncthreads();

        if (it == 0) {
#pragma unroll
            for (int ks = 0; ks < 8; ks++) {
                ldm_x4(aQ + ks * 32,       qhf[ks][0], qhf[ks][1], qhf[ks][2], qhf[ks][3]);
                ldm_x4(aQ + 256 + ks * 32, qlf[ks][0], qlf[ks][1], qlf[ks][2], qlf[ks][3]);
            }
        }

        const uint32_t so = (uint32_t)(it & 1) * FL_STAGE_B;

        float sAcc[8][4];
#pragma unroll
        for (int j = 0; j < 8; j++)
#pragma unroll
            for (int c = 0; c < 4; c++) sAcc[j][c] = 0.f;

        // ---- QK: 2 terms (Qh·Kh + Ql·Kh) over 64 KV cols
#pragma unroll
        for (int ks = 0; ks < 8; ks++) {
#pragma unroll
            for (int np = 0; np < 4; np++) {
                uint32_t kh[4];
                ldm_x4(kB[np] + so + ks * 32, kh[0], kh[1], kh[2], kh[3]);
#pragma unroll
                for (int f = 0; f < 2; f++)
                    mma16816(sAcc[2 * np + f], qhf[ks][0], qhf[ks][1], qhf[ks][2], qhf[ks][3],
                             kh[2 * f], kh[2 * f + 1]);
#pragma unroll
                for (int f = 0; f < 2; f++)
                    mma16816(sAcc[2 * np + f], qlf[ks][0], qlf[ks][1], qlf[ks][2], qlf[ks][3],
                             kh[2 * f], kh[2 * f + 1]);
            }
        }

        float rmax0 = -1e30f, rmax1 = -1e30f;
#pragma unroll
        for (int f = 0; f < 8; f++) {
            rmax0 = fmaxf(rmax0, fmaxf(sAcc[f][0], sAcc[f][1]));
            rmax1 = fmaxf(rmax1, fmaxf(sAcc[f][2], sAcc[f][3]));
        }
#pragma unroll
        for (int off = 1; off <= 2; off <<= 1) {
            rmax0 = fmaxf(rmax0, __shfl_xor_sync(0xffffffffu, rmax0, off));
            rmax1 = fmaxf(rmax1, __shfl_xor_sync(0xffffffffu, rmax1, off));
        }
        float mnew0 = fmaxf(mrow[0], rmax0);
        float mnew1 = fmaxf(mrow[1], rmax1);
        float cf0 = exp2f((mrow[0] - mnew0) * C2EXP);
        float cf1 = exp2f((mrow[1] - mnew1) * C2EXP);
        mrow[0] = mnew0; mrow[1] = mnew1;

#pragma unroll
        for (int j = 0; j < 16; j++) {
            oAcc[j][0] *= cf0; oAcc[j][1] *= cf0;
            oAcc[j][2] *= cf1; oAcc[j][3] *= cf1;
        }

        float sum0 = 0.f, sum1 = 0.f;
        uint32_t ph[4][4];
#pragma unroll
        for (int ks = 0; ks < 4; ks++) {
            float p[8];
#pragma unroll
            for (int f = 0; f < 2; f++) {
                float* s = sAcc[2 * ks + f];
                p[4 * f + 0] = exp2f((s[0] - mnew0) * C2EXP);
                p[4 * f + 1] = exp2f((s[1] - mnew0) * C2EXP);
                p[4 * f + 2] = exp2f((s[2] - mnew1) * C2EXP);
                p[4 * f + 3] = exp2f((s[3] - mnew1) * C2EXP);
            }
            sum0 += p[0] + p[1] + p[4] + p[5];
            sum1 += p[2] + p[3] + p[6] + p[7];
            ph[ks][0] = pack_h2(p[0], p[1]);
            ph[ks][1] = pack_h2(p[2], p[3]);
            ph[ks][2] = pack_h2(p[4], p[5]);
            ph[ks][3] = pack_h2(p[6], p[7]);
        }
#pragma unroll
        for (int off = 1; off <= 2; off <<= 1) {
            sum0 += __shfl_xor_sync(0xffffffffu, sum0, off);
            sum1 += __shfl_xor_sync(0xffffffffu, sum1, off);
        }
        lrow[0] = lrow[0] * cf0 + sum0;
        lrow[1] = lrow[1] * cf1 + sum1;

        // ---- PV: single term Ph·Vh
#pragma unroll
        for (int ks = 0; ks < 4; ks++) {
            const uint32_t vo = so + ks * (16 * KP * 2);
#pragma unroll
            for (int np = 0; np < 8; np++) {
                uint32_t vh[4];
                ldm_x4t(vB[np] + vo, vh[0], vh[1], vh[2], vh[3]);
#pragma unroll
                for (int f = 0; f < 2; f++)
                    mma16816(oAcc[2 * np + f], ph[ks][0], ph[ks][1], ph[ks][2], ph[ks][3],
                             vh[2 * f], vh[2 * f + 1]);
            }
        }

        __syncthreads();
        if (it + 2 < NKV) loadKV(it + 2, it & 1);
        else              cp_commit();
    }

    const float inv0 = 1.f / lrow[0];
    const float inv1 = 1.f / lrow[1];
    const int r0 = q0 + warp * 16 + (lane >> 2);
    const int colb = (lane & 3) * 2;
#pragma unroll
    for (int nj = 0; nj < 16; nj++) {
        const int col = h * HDIM + nj * 8 + colb;
        float o0 = oAcc[nj][0] * inv0, o1 = oAcc[nj][1] * inv0;
        float o2 = oAcc[nj][2] * inv1, o3 = oAcc[nj][3] * inv1;
        __half2 h01 = __floats2half2_rn(o0, o1);
        __half2 h23 = __floats2half2_rn(o2, o3);
        float2 f01 = __half22float2(h01);
        float2 f23 = __half22float2(h23);
        __half2 l01 = __floats2half2_rn(o0 - f01.x, o1 - f01.y);
        __half2 l23 = __floats2half2_rn(o2 - f23.x, o3 - f23.y);
        __half* b0 = ocat + (size_t)r0 * LK2 + col;
        __half* b1 = ocat + (size_t)(r0 + 8) * LK2 + col;
        *reinterpret_cast<__half2*>(b0)        = h01;
        *reinterpret_cast<__half2*>(b0 + DIM)  = l01;
        *reinterpret_cast<__half2*>(b1)        = h23;
        *reinterpret_cast<__half2*>(b1 + DIM)  = l23;
    }
}

// ---------------- launch ----------------
extern "C" void kernel_launch(void* const* d_in, const int* in_sizes, int n_in,
                              void* d_out, int out_size)
{
    (void)in_sizes; (void)n_in; (void)out_size;
    const float* x    = (const float*)d_in[0];
    const float* ehs  = (const float*)d_in[1];
    const float* rcos = (const float*)d_in[2];
    const float* rsin = (const float*)d_in[3];
    W8 w8 = {{ (const float*)d_in[4],  (const float*)d_in[5],
               (const float*)d_in[6],  (const float*)d_in[7],
               (const float*)d_in[8],  (const float*)d_in[9],
               (const float*)d_in[17], (const float*)d_in[19] }};
    const float* baq  = (const float*)d_in[10];
    const float* bak  = (const float*)d_in[11];
    const float* bav  = (const float*)d_in[12];
    const float* nqw  = (const float*)d_in[13];
    const float* nkw  = (const float*)d_in[14];
    const float* naqw = (const float*)d_in[15];
    const float* nakw = (const float*)d_in[16];
    const float* bo   = (const float*)d_in[18];
    const float* bao  = (const float*)d_in[20];
    float* out = (float*)d_out;

    __half *acat, *qg, *kg, *vg, *ocat, *wcat;
    cudaGetSymbolAddress((void**)&acat, g_acat);
    cudaGetSymbolAddress((void**)&qg,   g_qg);
    cudaGetSymbolAddress((void**)&kg,   g_kg);
    cudaGetSymbolAddress((void**)&vg,   g_vg);
    cudaGetSymbolAddress((void**)&ocat, g_ocat);
    cudaGetSymbolAddress((void**)&wcat, g_wcat);

    cudaFuncSetAttribute(qkv_fused_k, cudaFuncAttributeMaxDynamicSharedMemorySize, SMEM_BYTES);
    cudaFuncSetAttribute(outproj_k,   cudaFuncAttributeMaxDynamicSharedMemorySize, SMEM_BYTES);
    cudaFuncSetAttribute(flash_k,     cudaFuncAttributeMaxDynamicSharedMemorySize, FL_SMEM);

    const dim3 blk(256);
    const size_t WSTRIDE = (size_t)DIM * DIM;

    conv_hl_k<<<dim3((S_TXT * DIM / 4 + 255) / 256), blk>>>(ehs, acat, S_TXT, 0);
    conv_hl_k<<<dim3((S_IMG * DIM / 4 + 255) / 256), blk>>>(x,   acat, S_IMG, S_TXT);
    conv_w8_k<<<dim3((DIM * DIM / 4 + 255) / 256, 1, 8), blk>>>(w8, wcat);

    {
        PArgs pq = { wcat + 0 * WSTRIDE, wcat + 3 * WSTRIDE, baq, nqw, naqw, qg, 256 };
        PArgs pk = { wcat + 1 * WSTRIDE, wcat + 4 * WSTRIDE, bak, nkw, nakw, kg, 128 };
        PArgs pv = { wcat + 2 * WSTRIDE, wcat + 5 * WSTRIDE, bav, nullptr, nullptr, vg, 128 };
        qkv_fused_k<<<dim3(HEADS, S_TOT / 128, 3), blk, SMEM_BYTES>>>(
            acat, pq, pk, pv, rcos, rsin);
    }

    flash_k<<<dim3(S_TOT / FQ, HEADS), dim3(128), FL_SMEM>>>(qg, kg, vg, ocat);

    outproj_k<<<dim3(DIM / 128, S_TOT / 128), blk, SMEM_BYTES>>>(
        ocat, wcat + 6 * WSTRIDE, bo, wcat + 7 * WSTRIDE, bao, out);
}